// round 14
// baseline (speedup 1.0000x reference)
#include <cuda_runtime.h>
#include <cstdint>
#include <math.h>

// ---------------- problem constants ----------------
#define D_MODEL 1024
#define DFF_DIM 4096
#define NTOK    2048          // B*S = 2*1024
#define NHEAD   16
#define DH      64
#define NLAYER  3
#define NCHUNK  16            // chunks per sequence
#define CLEN    64            // tokens per chunk

// ---------------- scratch (no allocs allowed) ----------------
__device__ float g_cur[NTOK * D_MODEL];
__device__ float g_q  [NTOK * D_MODEL];
__device__ float g_k  [NTOK * D_MODEL];
__device__ float g_v  [NTOK * D_MODEL];
__device__ float g_h  [NTOK * D_MODEL];
__device__ float g_hr [NTOK * D_MODEL];      // tf32-rounded h (FFN1 A operand)
__device__ float g_xr [NTOK * D_MODEL];      // tf32-rounded activation (QKV A operand)
__device__ float g_ffn[NTOK * DFF_DIM];
__device__ float g_S  [32 * NCHUNK * DH * DH];
__device__ float g_Z  [32 * NCHUNK * DH];

// ================= helpers =================
__device__ __forceinline__ uint32_t f2tf32(float f) {
    uint32_t u;
    asm("cvt.rna.tf32.f32 %0, %1;" : "=r"(u) : "f"(f));
    return u;
}
__device__ __forceinline__ float roundtf(float f) {
    return __uint_as_float(f2tf32(f));
}
__device__ __forceinline__ uint32_t smem_u32(const void* p) {
    uint32_t a;
    asm("{ .reg .u64 t; cvta.to.shared.u64 t, %1; cvt.u32.u64 %0, t; }" : "=r"(a) : "l"(p));
    return a;
}
__device__ __forceinline__ void mma_tf32(float c[4], uint32_t a0, uint32_t a1,
                                         uint32_t a2, uint32_t a3,
                                         uint32_t b0, uint32_t b1) {
    asm volatile(
        "mma.sync.aligned.m16n8k8.row.col.f32.tf32.tf32.f32 "
        "{%0,%1,%2,%3}, {%4,%5,%6,%7}, {%8,%9}, {%0,%1,%2,%3};"
        : "+f"(c[0]), "+f"(c[1]), "+f"(c[2]), "+f"(c[3])
        : "r"(a0), "r"(a1), "r"(a2), "r"(a3), "r"(b0), "r"(b1));
}
#define CP16(dst, src) \
    asm volatile("cp.async.cg.shared.global [%0], [%1], 16;" :: "r"(dst), "l"(src) : "memory")
#define CP_COMMIT() asm volatile("cp.async.commit_group;" ::: "memory")
#define CP_WAIT0()  asm volatile("cp.async.wait_group 0;" ::: "memory")

// ---------------- tf32 rounding copy (layer-0 x only) ----------------
__global__ void round_kernel(const float* __restrict__ src, float* __restrict__ dst, int n4)
{
    int i = blockIdx.x * blockDim.x + threadIdx.x;
    if (i < n4) {
        float4 v = ((const float4*)src)[i];
        uint4 u;
        u.x = f2tf32(v.x); u.y = f2tf32(v.y);
        u.z = f2tf32(v.z); u.w = f2tf32(v.w);
        ((uint4*)dst)[i] = u;
    }
}

// ================= TF32 tensor-core GEMM — 256 thr, BK=32, 2 CTAs/SM =================
// A (activations, pre-rounded): cp.async. B (weights): LDG->cvt->STS.
// A layout: 128 x 32 per chunk, stride 36 (round-4 proven conflict-free).
// B layout: 32 x 128 per chunk, stride 168 with 4-word pad per 32 data words
//           (round-8 proven conflict-free for staging and frag reads).
#define BK      32
#define ASTRIDE 36
#define BSTRIDE 168
#define ABUF (128 * ASTRIDE)              // 4608 words
#define BBUF (32 * BSTRIDE)               // 5376 words
#define GEMM_SMEM ((2 * ABUF + 2 * BBUF) * 4)   // 79872 bytes -> 2 CTAs/SM

__global__ __launch_bounds__(256, 2) void mma_gemm(
    const float* __restrict__ A,
    const float* __restrict__ B0, const float* __restrict__ B1, const float* __restrict__ B2,
    const float* __restrict__ bias0, const float* __restrict__ bias1, const float* __restrict__ bias2,
    float* __restrict__ C0, float* __restrict__ C1, float* __restrict__ C2,
    int M, int N, int K, int do_relu)
{
    extern __shared__ float sm[];
    const uint32_t smb = smem_u32(sm);

    const int z = blockIdx.z;
    const float* B    = (z == 0) ? B0 : (z == 1) ? B1 : B2;
    const float* bias = (z == 0) ? bias0 : (z == 1) ? bias1 : bias2;
    float* C          = (z == 0) ? C0 : (z == 1) ? C1 : C2;

    const int tid  = threadIdx.x;
    const int bm   = blockIdx.y * 128;
    const int bn   = blockIdx.x * 128;
    const int lane = tid & 31;
    const int warp = tid >> 5;          // 0..7
    const int g    = lane >> 2;
    const int t    = lane & 3;
    const int m0   = (warp & 1) * 64;   // 2 m-warps
    const int n0   = (warp >> 1) * 32;  // 4 n-warps

    float acc[4][4][4];
    #pragma unroll
    for (int i = 0; i < 4; i++)
        #pragma unroll
        for (int j = 0; j < 4; j++)
            #pragma unroll
            for (int e = 0; e < 4; e++) acc[i][j][e] = 0.f;

    // staging indices (256 threads, one BK=32 chunk)
    const int ar = tid >> 1;              // 0..127
    const int ac = (tid & 1) * 16;        // 0 or 16
    const int br = tid >> 3;              // 0..31
    const int bc = (tid & 7) * 16;        // 0..112
    const int bcp = bc + ((bc >> 5) << 2);

    const float* Abase = A + (size_t)(bm + ar) * K + ac;
    const float* Bbase = B + (size_t)br * N + bn + bc;
    const uint32_t aoff = 4u * (uint32_t)(ar * ASTRIDE + ac);

    int cnp[4];
    #pragma unroll
    for (int nf = 0; nf < 4; nf++) {
        const int cb = n0 + nf * 8;
        cnp[nf] = cb + ((cb >> 5) << 2) + g;
    }

    const int NC = K / BK;

    // A: 16 words per thread via 4 cp.async (chunk k0 -> buffer buf)
    auto issueA = [&](int buf, int k0) {
        const float* asrc = Abase + k0;
        uint32_t adst = smb + 4u * (uint32_t)(buf * ABUF) + aoff;
        CP16(adst,       asrc);
        CP16(adst + 16u, asrc + 4);
        CP16(adst + 32u, asrc + 8);
        CP16(adst + 48u, asrc + 12);
    };
    // B: 16 words per thread
    auto ldgB = [&](int k0, float4 pb[4]) {
        const float* bsrc = Bbase + (size_t)k0 * N;
        pb[0] = *(const float4*)(bsrc);
        pb[1] = *(const float4*)(bsrc + 4);
        pb[2] = *(const float4*)(bsrc + 8);
        pb[3] = *(const float4*)(bsrc + 12);
    };
    auto stsB = [&](float* Bd, const float4 pb[4]) {
        #pragma unroll
        for (int i = 0; i < 4; i++) {
            uint4 u;
            u.x = f2tf32(pb[i].x); u.y = f2tf32(pb[i].y);
            u.z = f2tf32(pb[i].z); u.w = f2tf32(pb[i].w);
            *(uint4*)(Bd + br * BSTRIDE + bcp + i * 4) = u;
        }
    };

    // ---- prologue: chunk 0 ----
    issueA(0, 0);
    CP_COMMIT();
    {
        float4 pb[4];
        ldgB(0, pb);
        stsB(sm + 2 * ABUF, pb);
    }
    CP_WAIT0();
    __syncthreads();

    for (int c = 0; c < NC; c++) {
        const int buf = c & 1;
        const int nb  = buf ^ 1;
        const bool more = (c + 1 < NC);
        float4 pb[4];

        if (more) {
            issueA(nb, (c + 1) * BK);
            CP_COMMIT();
            ldgB((c + 1) * BK, pb);
        }

        const uint32_t* Au = (const uint32_t*)(sm + buf * ABUF);
        const uint32_t* Bu = (const uint32_t*)(sm + 2 * ABUF + buf * BBUF);

        #pragma unroll
        for (int ks = 0; ks < 4; ks++) {
            const int kk = ks * 8;
            uint32_t af[4][4];
            #pragma unroll
            for (int mf = 0; mf < 4; mf++) {
                const int r = m0 + mf * 16 + g;
                af[mf][0] = Au[r * ASTRIDE + kk + t];
                af[mf][1] = Au[(r + 8) * ASTRIDE + kk + t];
                af[mf][2] = Au[r * ASTRIDE + kk + t + 4];
                af[mf][3] = Au[(r + 8) * ASTRIDE + kk + t + 4];
            }
            #pragma unroll
            for (int nf = 0; nf < 4; nf++) {
                uint32_t b0 = Bu[(kk + t) * BSTRIDE + cnp[nf]];
                uint32_t b1 = Bu[(kk + t + 4) * BSTRIDE + cnp[nf]];
                #pragma unroll
                for (int mf = 0; mf < 4; mf++)
                    mma_tf32(acc[mf][nf], af[mf][0], af[mf][1], af[mf][2], af[mf][3], b0, b1);
            }
        }

        if (more) {
            stsB(sm + 2 * ABUF + nb * BBUF, pb);
            CP_WAIT0();
            __syncthreads();
        }
    }

    #pragma unroll
    for (int mf = 0; mf < 4; mf++) {
        const int r0 = bm + m0 + mf * 16 + g;
        #pragma unroll
        for (int nf = 0; nf < 4; nf++) {
            const int col = bn + n0 + nf * 8 + 2 * t;
            const float b0 = bias[col], b1 = bias[col + 1];
            float2 o0, o1;
            o0.x = acc[mf][nf][0] + b0; o0.y = acc[mf][nf][1] + b1;
            o1.x = acc[mf][nf][2] + b0; o1.y = acc[mf][nf][3] + b1;
            if (do_relu) {
                o0.x = roundtf(fmaxf(o0.x, 0.f)); o0.y = roundtf(fmaxf(o0.y, 0.f));
                o1.x = roundtf(fmaxf(o1.x, 0.f)); o1.y = roundtf(fmaxf(o1.y, 0.f));
            }
            *(float2*)(C + (size_t)r0 * N + col)       = o0;
            *(float2*)(C + (size_t)(r0 + 8) * N + col) = o1;
        }
    }
}

// ============ chunked causal linear attention with fused FAVOR ============
#define CST 68   // smem tile stride (words)
#define OMS 33   // omega smem stride

__device__ __forceinline__ void load_tile(
    float* dst, const float* __restrict__ src, size_t gbase, int tid)
{
    const int t = tid >> 2;
    const int qo = (tid & 3) * 16;
    const float* p = src + gbase + (size_t)t * D_MODEL + qo;
    float* d = dst + t * CST + qo;
    #pragma unroll
    for (int i = 0; i < 4; i++)
        *(float4*)(d + i * 4) = *(const float4*)(p + i * 4);
}

__device__ __forceinline__ void favor_uh(
    const float* __restrict__ row, const float* __restrict__ om,
    int grp, float u[8], float& h)
{
    const float scale = 0.35355339059327373f;   // 64^-0.25
    #pragma unroll
    for (int jj = 0; jj < 8; jj++) u[jj] = 0.f;
    h = 0.f;
    #pragma unroll 4
    for (int d = 0; d < DH; d++) {
        const float xs = row[d] * scale;
        h = fmaf(xs, xs, h);
        const float* omd = om + d * OMS + grp * 8;
        #pragma unroll
        for (int jj = 0; jj < 8; jj++)
            u[jj] = fmaf(xs, omd[jj], u[jj]);
    }
    h *= 0.5f;
}

#define SUMS_SMEM ((3 * 64 * CST + 64 * OMS) * 4)
__global__ __launch_bounds__(256) void chunk_sums_kernel(
    const float* __restrict__ Kraw, const float* __restrict__ V,
    const float* __restrict__ omega,
    float* __restrict__ gS, float* __restrict__ gZ)
{
    extern __shared__ float s1[];
    float* kr = s1;
    float* vs = s1 + 64 * CST;
    float* kf = s1 + 2 * 64 * CST;
    float* om = s1 + 3 * 64 * CST;

    const int ch = blockIdx.x;
    const int bh = blockIdx.y;
    const int tid = threadIdx.x;
    const int b = bh >> 4, hd = bh & 15;
    const size_t gbase = (size_t)b * 1024 * D_MODEL + (size_t)(ch * CLEN) * D_MODEL + hd * DH;

    load_tile(kr, Kraw, gbase, tid);
    load_tile(vs, V,  gbase, tid);
    for (int i = tid; i < DH * 32; i += 256)
        om[(i >> 5) * OMS + (i & 31)] = omega[i];
    __syncthreads();

    {
        const int tok = tid >> 2, grp = tid & 3;
        float u[8], h;
        favor_uh(kr + tok * CST, om, grp, u, h);
        float* kfr = kf + tok * CST + grp * 8;
        #pragma unroll
        for (int jj = 0; jj < 8; jj++) {
            kfr[jj]      = expf(u[jj]  - h) * 0.125f;
            kfr[32 + jj] = expf(-u[jj] - h) * 0.125f;
        }
    }
    __syncthreads();

    const int mg = (tid >> 4) * 4;
    const int dg = (tid & 15) * 4;

    float acc[4][4];
    float zz[4];
    #pragma unroll
    for (int e = 0; e < 4; e++) {
        zz[e] = 0.f;
        #pragma unroll
        for (int c = 0; c < 4; c++) acc[e][c] = 0.f;
    }

    #pragma unroll 4
    for (int t = 0; t < CLEN; t++) {
        float4 v4 = *(const float4*)(vs + t * CST + dg);
        #pragma unroll
        for (int e = 0; e < 4; e++) {
            const float kv = kf[t * CST + mg + e];
            zz[e] += kv;
            acc[e][0] = fmaf(kv, v4.x, acc[e][0]);
            acc[e][1] = fmaf(kv, v4.y, acc[e][1]);
            acc[e][2] = fmaf(kv, v4.z, acc[e][2]);
            acc[e][3] = fmaf(kv, v4.w, acc[e][3]);
        }
    }

    const size_t idx = (size_t)(bh * NCHUNK + ch);
    #pragma unroll
    for (int e = 0; e < 4; e++)
        *(float4*)(gS + idx * 4096 + (size_t)(mg + e) * 64 + dg) =
            make_float4(acc[e][0], acc[e][1], acc[e][2], acc[e][3]);
    if ((tid & 15) == 0) {
        #pragma unroll
        for (int e = 0; e < 4; e++) gZ[idx * 64 + mg + e] = zz[e];
    }
}

__global__ __launch_bounds__(256) void chunk_prefix_kernel(
    float* __restrict__ gS, float* __restrict__ gZ)
{
    const int gid = blockIdx.x * 256 + threadIdx.x;   // 0 .. 131071
    const int bh = gid >> 12;
    const int e  = gid & 4095;

    const size_t base = (size_t)bh * (NCHUNK * 4096) + e;
    float vals[NCHUNK];
    #pragma unroll
    for (int ch = 0; ch < NCHUNK; ch++)
        vals[ch] = gS[base + (size_t)ch * 4096];

    float run = 0.f;
    #pragma unroll
    for (int ch = 0; ch < NCHUNK; ch++) {
        const float t = vals[ch];
        gS[base + (size_t)ch * 4096] = run;
        run += t;
    }

    if (e < 64) {
        const size_t zbase = (size_t)bh * (NCHUNK * 64) + e;
        float zv[NCHUNK];
        #pragma unroll
        for (int ch = 0; ch < NCHUNK; ch++)
            zv[ch] = gZ[zbase + ch * 64];
        float zr = 0.f;
        #pragma unroll
        for (int ch = 0; ch < NCHUNK; ch++) {
            const float t = zv[ch];
            gZ[zbase + ch * 64] = zr;
            zr += t;
        }
    }
}

#define ATTN_SMEM ((5 * 64 * CST + 64 + 64 * OMS) * 4)
__global__ __launch_bounds__(256) void chunk_attn_kernel(
    const float* __restrict__ Qraw, const float* __restrict__ Kraw,
    const float* __restrict__ V, const float* __restrict__ omega,
    const float* __restrict__ gS, const float* __restrict__ gZ,
    float* __restrict__ Out)
{
    extern __shared__ float smw[];
    float* qs = smw;
    float* kt = smw + 64 * CST;
    float* vs = smw + 2 * 64 * CST;
    float* Sp = smw + 3 * 64 * CST;
    float* Am = smw + 4 * 64 * CST;
    float* zp = smw + 5 * 64 * CST;
    float* om = smw + 5 * 64 * CST + 64;

    const int ch = blockIdx.x;
    const int bh = blockIdx.y;
    const int tid = threadIdx.x;
    const int b = bh >> 4, hd = bh & 15;
    const size_t gbase = (size_t)b * 1024 * D_MODEL + (size_t)(ch * CLEN) * D_MODEL + hd * DH;
    const size_t idx = (size_t)(bh * NCHUNK + ch);

    load_tile(qs, Qraw, gbase, tid);
    load_tile(Am, Kraw, gbase, tid);
    load_tile(vs, V,  gbase, tid);
    {
        const int m = tid >> 2;
        const int qo = (tid & 3) * 16;
        const float* p = gS + idx * 4096 + (size_t)m * 64 + qo;
        float* dp = Sp + m * CST + qo;
        #pragma unroll
        for (int i = 0; i < 4; i++)
            *(float4*)(dp + i * 4) = *(const float4*)(p + i * 4);
    }
    if (tid < 64) zp[tid] = gZ[idx * 64 + tid];
    for (int i = tid; i < DH * 32; i += 256)
        om[(i >> 5) * OMS + (i & 31)] = omega[i];
    __syncthreads();

    const int tok = tid >> 2, grp = tid & 3;
    float uq[8], hq, uk[8], hk;
    favor_uh(qs + tok * CST, om, grp, uq, hq);
    favor_uh(Am + tok * CST, om, grp, uk, hk);
    __syncthreads();

    {
        float* qfr = qs + tok * CST + grp * 8;
        #pragma unroll
        for (int jj = 0; jj < 8; jj++) {
            qfr[jj]      = expf(uq[jj]  - hq) * 0.125f;
            qfr[32 + jj] = expf(-uq[jj] - hq) * 0.125f;
        }
        const int jb = grp * 8;
        #pragma unroll
        for (int jj = 0; jj < 8; jj++) {
            kt[(jb + jj) * CST + tok]      = expf(uk[jj]  - hk) * 0.125f;
            kt[(32 + jb + jj) * CST + tok] = expf(-uk[jj] - hk) * 0.125f;
        }
    }
    __syncthreads();

    const int ig = (tid >> 4) * 4;
    const int jg = (tid & 15) * 4;

    float a[4][4];
    float qz[4];
    #pragma unroll
    for (int e = 0; e < 4; e++) {
        qz[e] = 0.f;
        #pragma unroll
        for (int c = 0; c < 4; c++) a[e][c] = 0.f;
    }
    #pragma unroll 4
    for (int m = 0; m < DH; m++) {
        const float zv = zp[m];
        float4 k4 = *(const float4*)(kt + m * CST + jg);
        #pragma unroll
        for (int e = 0; e < 4; e++) {
            const float qv = qs[(ig + e) * CST + m];
            qz[e] = fmaf(qv, zv, qz[e]);
            a[e][0] = fmaf(qv, k4.x, a[e][0]);
            a[e][1] = fmaf(qv, k4.y, a[e][1]);
            a[e][2] = fmaf(qv, k4.z, a[e][2]);
            a[e][3] = fmaf(qv, k4.w, a[e][3]);
        }
    }
    float den[4];
    #pragma unroll
    for (int e = 0; e < 4; e++) {
        const int i = ig + e;
        #pragma unroll
        for (int c = 0; c < 4; c++)
            if (jg + c > i) a[e][c] = 0.f;
        float rs = a[e][0] + a[e][1] + a[e][2] + a[e][3];
        rs += __shfl_xor_sync(0xffffffffu, rs, 1);
        rs += __shfl_xor_sync(0xffffffffu, rs, 2);
        rs += __shfl_xor_sync(0xffffffffu, rs, 4);
        rs += __shfl_xor_sync(0xffffffffu, rs, 8);
        den[e] = qz[e] + rs + 1e-6f;
        *(float4*)(Am + i * CST + jg) = make_float4(a[e][0], a[e][1], a[e][2], a[e][3]);
    }
    __syncthreads();

    float acc[4][4];
    #pragma unroll
    for (int e = 0; e < 4; e++)
        #pragma unroll
        for (int c = 0; c < 4; c++) acc[e][c] = 0.f;

    #pragma unroll 4
    for (int m = 0; m < DH; m++) {
        float4 s4 = *(const float4*)(Sp + m * CST + jg);
        #pragma unroll
        for (int e = 0; e < 4; e++) {
            const float qv = qs[(ig + e) * CST + m];
            acc[e][0] = fmaf(qv, s4.x, acc[e][0]);
            acc[e][1] = fmaf(qv, s4.y, acc[e][1]);
            acc[e][2] = fmaf(qv, s4.z, acc[e][2]);
            acc[e][3] = fmaf(qv, s4.w, acc[e][3]);
        }
    }
    const int jmax = ig + 3;
    for (int j = 0; j <= jmax; j++) {
        float4 v4 = *(const float4*)(vs + j * CST + jg);
        #pragma unroll
        for (int e = 0; e < 4; e++) {
            const float av = Am[(ig + e) * CST + j];
            acc[e][0] = fmaf(av, v4.x, acc[e][0]);
            acc[e][1] = fmaf(av, v4.y, acc[e][1]);
            acc[e][2] = fmaf(av, v4.z, acc[e][2]);
            acc[e][3] = fmaf(av, v4.w, acc[e][3]);
        }
    }

    #pragma unroll
    for (int e = 0; e < 4; e++) {
        const float inv = 1.f / den[e];
        float* op = Out + gbase + (size_t)(ig + e) * D_MODEL + jg;
        *(float4*)op = make_float4(roundtf(acc[e][0] * inv), roundtf(acc[e][1] * inv),
                                   roundtf(acc[e][2] * inv), roundtf(acc[e][3] * inv));
    }
}

// ---------------- LayerNorm: out = LN(a + r) * g + b ; optional rounded copy ----------------
__global__ __launch_bounds__(256) void ln_kernel(
    float* __restrict__ out, const float* __restrict__ a,
    const float* __restrict__ r, const float* __restrict__ gam,
    const float* __restrict__ bet, float* __restrict__ outr)
{
    const int row = blockIdx.x;
    const int tid = threadIdx.x;
    const float* pa = a + (size_t)row * D_MODEL;
    const float* pr = r + (size_t)row * D_MODEL;

    float v[4];
    float s = 0.f, ss = 0.f;
    #pragma unroll
    for (int i = 0; i < 4; i++) {
        int idx = tid + i * 256;
        float t = pa[idx] + pr[idx];
        v[i] = t; s += t; ss = fmaf(t, t, ss);
    }

    __shared__ float red[18];
    #pragma unroll
    for (int o = 16; o; o >>= 1) {
        s  += __shfl_xor_sync(0xffffffffu, s,  o);
        ss += __shfl_xor_sync(0xffffffffu, ss, o);
    }
    const int w = tid >> 5, lane = tid & 31;
    __shared__ float rw[16];
    if (lane == 0) { rw[w] = s; rw[w + 8] = ss; }
    __syncthreads();
    if (tid == 0) {
        float S0 = 0.f, S1 = 0.f;
        #pragma unroll
        for (int i = 0; i < 8; i++) { S0 += rw[i]; S1 += rw[i + 8]; }
        red[16] = S0; red[17] = S1;
    }
    __syncthreads();

    const float mean = red[16] * (1.f / 1024.f);
    const float var  = red[17] * (1.f / 1024.f) - mean * mean;
    const float inv  = rsqrtf(var + 1e-5f);

    float* po = out + (size_t)row * D_MODEL;
    float* pq = (outr != nullptr) ? outr + (size_t)row * D_MODEL : nullptr;
    #pragma unroll
    for (int i = 0; i < 4; i++) {
        int idx = tid + i * 256;
        float o = (v[i] - mean) * inv * gam[idx] + bet[idx];
        po[idx] = o;
        if (pq) pq[idx] = roundtf(o);
    }
}

// ---------------- launch ----------------
extern "C" void kernel_launch(void* const* d_in, const int* in_sizes, int n_in,
                              void* d_out, int out_size)
{
    const float* x    = (const float*)d_in[0];
    const float* Wq   = (const float*)d_in[1];
    const float* bq   = (const float*)d_in[2];
    const float* Wk   = (const float*)d_in[3];
    const float* bk   = (const float*)d_in[4];
    const float* Wv   = (const float*)d_in[5];
    const float* bv   = (const float*)d_in[6];
    const float* Wo   = (const float*)d_in[7];
    const float* bo   = (const float*)d_in[8];
    const float* omg  = (const float*)d_in[9];
    const float* ln1g = (const float*)d_in[10];
    const float* ln1b = (const float*)d_in[11];
    const float* ln2g = (const float*)d_in[12];
    const float* ln2b = (const float*)d_in[13];
    const float* W1   = (const float*)d_in[14];
    const float* bf1  = (const float*)d_in[15];
    const float* W2   = (const float*)d_in[16];
    const float* bf2  = (const float*)d_in[17];
    float* out = (float*)d_out;

    float *cur, *q, *k, *v, *h, *hr, *xr, *ffn, *gS, *gZ;
    cudaGetSymbolAddress((void**)&cur, g_cur);
    cudaGetSymbolAddress((void**)&q,   g_q);
    cudaGetSymbolAddress((void**)&k,   g_k);
    cudaGetSymbolAddress((void**)&v,   g_v);
    cudaGetSymbolAddress((void**)&h,   g_h);
    cudaGetSymbolAddress((void**)&hr,  g_hr);
    cudaGetSymbolAddress((void**)&xr,  g_xr);
    cudaGetSymbolAddress((void**)&ffn, g_ffn);
    cudaGetSymbolAddress((void**)&gS,  g_S);
    cudaGetSymbolAddress((void**)&gZ,  g_Z);

    cudaFuncSetAttribute(mma_gemm, cudaFuncAttributeMaxDynamicSharedMemorySize, GEMM_SMEM);
    cudaFuncSetAttribute(chunk_sums_kernel, cudaFuncAttributeMaxDynamicSharedMemorySize, SUMS_SMEM);
    cudaFuncSetAttribute(chunk_attn_kernel, cudaFuncAttributeMaxDynamicSharedMemorySize, ATTN_SMEM);

    // prep: tf32-round layer-0 activation
    const int nX4 = NTOK * D_MODEL / 4;
    round_kernel<<<nX4 / 256, 256>>>(x, xr, nX4);

    const dim3 gQKV(D_MODEL / 128, NTOK / 128, 3);
    const dim3 gD(D_MODEL / 128, NTOK / 128, 1);
    const dim3 gF(DFF_DIM / 128, NTOK / 128, 1);
    const dim3 gCh(NCHUNK, 32);
    const int  gPref = (32 * 4096) / 256;

    for (int l = 0; l < NLAYER; l++) {
        const size_t wDD  = (size_t)l * D_MODEL * D_MODEL;
        const size_t wDF  = (size_t)l * D_MODEL * DFF_DIM;
        const size_t bD   = (size_t)l * D_MODEL;
        const size_t bF   = (size_t)l * DFF_DIM;
        const size_t oOff = (size_t)l * DH * 32;
        const float* resA = (l == 0) ? x : cur;

        mma_gemm<<<gQKV, 256, GEMM_SMEM>>>(xr,
            Wq + wDD, Wk + wDD, Wv + wDD,
            bq + bD, bk + bD, bv + bD,
            q, k, v, NTOK, D_MODEL, D_MODEL, 0);

        chunk_sums_kernel<<<gCh, 256, SUMS_SMEM>>>(k, v, omg + oOff, gS, gZ);
        chunk_prefix_kernel<<<gPref, 256>>>(gS, gZ);
        chunk_attn_kernel<<<gCh, 256, ATTN_SMEM>>>(q, k, v, omg + oOff, gS, gZ, q);

        mma_gemm<<<gD, 256, GEMM_SMEM>>>(q,
            Wo + wDD, Wo + wDD, Wo + wDD,
            bo + bD, bo + bD, bo + bD,
            k, k, k, NTOK, D_MODEL, D_MODEL, 0);
        ln_kernel<<<NTOK, 256>>>(h, resA, k, ln1g + bD, ln1b + bD, hr);

        mma_gemm<<<gF, 256, GEMM_SMEM>>>(hr,
            W1 + wDF, W1 + wDF, W1 + wDF,
            bf1 + bF, bf1 + bF, bf1 + bF,
            ffn, ffn, ffn, NTOK, DFF_DIM, D_MODEL, 1);
        mma_gemm<<<gD, 256, GEMM_SMEM>>>(ffn,
            W2 + wDF, W2 + wDF, W2 + wDF,
            bf2 + bD, bf2 + bD, bf2 + bD,
            v, v, v, NTOK, D_MODEL, DFF_DIM, 0);

        const bool last = (l == NLAYER - 1);
        float* dst = last ? out : cur;
        ln_kernel<<<NTOK, 256>>>(dst, h, v, ln2g + bD, ln2b + bD, last ? nullptr : xr);
    }
}

// round 15
// speedup vs baseline: 1.1142x; 1.1142x over previous
#include <cuda_runtime.h>
#include <cstdint>
#include <math.h>

// ---------------- problem constants ----------------
#define D_MODEL 1024
#define DFF_DIM 4096
#define NTOK    2048          // B*S = 2*1024
#define NHEAD   16
#define DH      64
#define NLAYER  3
#define NCHUNK  16            // chunks per sequence
#define CLEN    64            // tokens per chunk

// ---------------- scratch (no allocs allowed) ----------------
__device__ float g_cur[NTOK * D_MODEL];
__device__ float g_q  [NTOK * D_MODEL];
__device__ float g_k  [NTOK * D_MODEL];
__device__ float g_v  [NTOK * D_MODEL];
__device__ float g_h  [NTOK * D_MODEL];
__device__ float g_hr [NTOK * D_MODEL];      // tf32-rounded h (FFN1 A operand)
__device__ float g_xr [NTOK * D_MODEL];      // tf32-rounded activation (QKV A operand)
__device__ float g_ffn[NTOK * DFF_DIM];
__device__ float g_S  [32 * NCHUNK * DH * DH];
__device__ float g_Z  [32 * NCHUNK * DH];

// ================= helpers =================
__device__ __forceinline__ uint32_t f2tf32(float f) {
    uint32_t u;
    asm("cvt.rna.tf32.f32 %0, %1;" : "=r"(u) : "f"(f));
    return u;
}
__device__ __forceinline__ float roundtf(float f) {
    return __uint_as_float(f2tf32(f));
}
__device__ __forceinline__ uint32_t smem_u32(const void* p) {
    uint32_t a;
    asm("{ .reg .u64 t; cvta.to.shared.u64 t, %1; cvt.u32.u64 %0, t; }" : "=r"(a) : "l"(p));
    return a;
}
__device__ __forceinline__ void mma_tf32(float c[4], uint32_t a0, uint32_t a1,
                                         uint32_t a2, uint32_t a3,
                                         uint32_t b0, uint32_t b1) {
    asm volatile(
        "mma.sync.aligned.m16n8k8.row.col.f32.tf32.tf32.f32 "
        "{%0,%1,%2,%3}, {%4,%5,%6,%7}, {%8,%9}, {%0,%1,%2,%3};"
        : "+f"(c[0]), "+f"(c[1]), "+f"(c[2]), "+f"(c[3])
        : "r"(a0), "r"(a1), "r"(a2), "r"(a3), "r"(b0), "r"(b1));
}
#define CP16(dst, src) \
    asm volatile("cp.async.cg.shared.global [%0], [%1], 16;" :: "r"(dst), "l"(src) : "memory")
#define CP_COMMIT() asm volatile("cp.async.commit_group;" ::: "memory")
#define CP_WAIT0()  asm volatile("cp.async.wait_group 0;" ::: "memory")

// ---------------- tf32 rounding copy (layer-0 x only) ----------------
__global__ void round_kernel(const float* __restrict__ src, float* __restrict__ dst, int n4)
{
    int i = blockIdx.x * blockDim.x + threadIdx.x;
    if (i < n4) {
        float4 v = ((const float4*)src)[i];
        uint4 u;
        u.x = f2tf32(v.x); u.y = f2tf32(v.y);
        u.z = f2tf32(v.z); u.w = f2tf32(v.w);
        ((uint4*)dst)[i] = u;
    }
}

// ================= TF32 tensor-core GEMM — hybrid staging (round-13 proven) =================
#define BK      64
#define ASTRIDE 68
#define BSTRIDE 168
#define ABUF (128 * ASTRIDE)
#define BBUF (64 * BSTRIDE)
#define GEMM_SMEM ((2 * ABUF + 2 * BBUF) * 4)

__global__ __launch_bounds__(512, 1) void mma_gemm(
    const float* __restrict__ A,
    const float* __restrict__ B0, const float* __restrict__ B1, const float* __restrict__ B2,
    const float* __restrict__ bias0, const float* __restrict__ bias1, const float* __restrict__ bias2,
    float* __restrict__ C0, float* __restrict__ C1, float* __restrict__ C2,
    int M, int N, int K, int do_relu)
{
    extern __shared__ float sm[];
    const uint32_t smb = smem_u32(sm);

    const int z = blockIdx.z;
    const float* B    = (z == 0) ? B0 : (z == 1) ? B1 : B2;
    const float* bias = (z == 0) ? bias0 : (z == 1) ? bias1 : bias2;
    float* C          = (z == 0) ? C0 : (z == 1) ? C1 : C2;

    const int tid  = threadIdx.x;
    const int bm   = blockIdx.y * 128;
    const int bn   = blockIdx.x * 128;
    const int lane = tid & 31;
    const int warp = tid >> 5;          // 0..15
    const int g    = lane >> 2;
    const int t    = lane & 3;
    const int m0   = (warp & 3) * 32;
    const int n0   = (warp >> 2) * 32;

    float acc[2][4][4];
    #pragma unroll
    for (int i = 0; i < 2; i++)
        #pragma unroll
        for (int j = 0; j < 4; j++)
            #pragma unroll
            for (int e = 0; e < 4; e++) acc[i][j][e] = 0.f;

    const int ar = tid >> 2;              // 0..127
    const int ac = (tid & 3) * 8;         // 0,8,16,24
    const int br = tid >> 4;              // 0..31
    const int bc = (tid & 15) * 8;        // 0..120
    const int bcp = bc + ((bc >> 5) << 2);

    const float* Abase = A + (size_t)(bm + ar) * K + ac;
    const float* Bbase = B + (size_t)br * N + bn + bc;
    const uint32_t aoff = 4u * (uint32_t)(ar * ASTRIDE + ac);

    int cnp[4];
    #pragma unroll
    for (int nf = 0; nf < 4; nf++) {
        const int cb = n0 + nf * 8;
        cnp[nf] = cb + ((cb >> 5) << 2) + g;
    }

    const int NC = K / BK;

    auto issueA = [&](int buf, int k0) {
        #pragma unroll
        for (int half = 0; half < 2; half++) {
            const int koff = half * 32;
            const float* asrc = Abase + k0 + koff;
            uint32_t adst = smb + 4u * (uint32_t)(buf * ABUF) + aoff + 4u * (uint32_t)koff;
            CP16(adst, asrc);
            CP16(adst + 16u, asrc + 4);
        }
    };
    auto ldgB = [&](int k0, int koff, float4 pb[2]) {
        const float* bsrc = Bbase + (size_t)(k0 + koff) * N;
        pb[0] = *(const float4*)(bsrc);
        pb[1] = *(const float4*)(bsrc + 4);
    };
    auto stsB = [&](float* Bd, int koff, const float4 pb[2]) {
        #pragma unroll
        for (int i = 0; i < 2; i++) {
            uint4 u;
            u.x = f2tf32(pb[i].x); u.y = f2tf32(pb[i].y);
            u.z = f2tf32(pb[i].z); u.w = f2tf32(pb[i].w);
            *(uint4*)(Bd + (koff + br) * BSTRIDE + bcp + i * 4) = u;
        }
    };

    issueA(0, 0);
    CP_COMMIT();
    {
        float4 pb[2];
        ldgB(0, 0, pb);  stsB(sm + 2 * ABUF, 0, pb);
        ldgB(0, 32, pb); stsB(sm + 2 * ABUF, 32, pb);
    }
    CP_WAIT0();
    __syncthreads();

    for (int c = 0; c < NC; c++) {
        const int buf = c & 1;
        const int nb  = buf ^ 1;
        const bool more = (c + 1 < NC);
        float* Bd = sm + 2 * ABUF + nb * BBUF;
        float4 pb[2];

        if (more) {
            issueA(nb, (c + 1) * BK);
            CP_COMMIT();
            ldgB((c + 1) * BK, 0, pb);
        }

        const uint32_t* Au = (const uint32_t*)(sm + buf * ABUF);
        const uint32_t* Bu = (const uint32_t*)(sm + 2 * ABUF + buf * BBUF);

        #pragma unroll
        for (int ks = 0; ks < 4; ks++) {
            const int kk = ks * 8;
            uint32_t af[2][4];
            #pragma unroll
            for (int mf = 0; mf < 2; mf++) {
                const int r = m0 + mf * 16 + g;
                af[mf][0] = Au[r * ASTRIDE + kk + t];
                af[mf][1] = Au[(r + 8) * ASTRIDE + kk + t];
                af[mf][2] = Au[r * ASTRIDE + kk + t + 4];
                af[mf][3] = Au[(r + 8) * ASTRIDE + kk + t + 4];
            }
            #pragma unroll
            for (int nf = 0; nf < 4; nf++) {
                uint32_t b0 = Bu[(kk + t) * BSTRIDE + cnp[nf]];
                uint32_t b1 = Bu[(kk + t + 4) * BSTRIDE + cnp[nf]];
                #pragma unroll
                for (int mf = 0; mf < 2; mf++)
                    mma_tf32(acc[mf][nf], af[mf][0], af[mf][1], af[mf][2], af[mf][3], b0, b1);
            }
        }

        if (more) {
            stsB(Bd, 0, pb);
            ldgB((c + 1) * BK, 32, pb);
        }

        #pragma unroll
        for (int ks = 4; ks < 8; ks++) {
            const int kk = ks * 8;
            uint32_t af[2][4];
            #pragma unroll
            for (int mf = 0; mf < 2; mf++) {
                const int r = m0 + mf * 16 + g;
                af[mf][0] = Au[r * ASTRIDE + kk + t];
                af[mf][1] = Au[(r + 8) * ASTRIDE + kk + t];
                af[mf][2] = Au[r * ASTRIDE + kk + t + 4];
                af[mf][3] = Au[(r + 8) * ASTRIDE + kk + t + 4];
            }
            #pragma unroll
            for (int nf = 0; nf < 4; nf++) {
                uint32_t b0 = Bu[(kk + t) * BSTRIDE + cnp[nf]];
                uint32_t b1 = Bu[(kk + t + 4) * BSTRIDE + cnp[nf]];
                #pragma unroll
                for (int mf = 0; mf < 2; mf++)
                    mma_tf32(acc[mf][nf], af[mf][0], af[mf][1], af[mf][2], af[mf][3], b0, b1);
            }
        }

        if (more) {
            stsB(Bd, 32, pb);
            CP_WAIT0();
            __syncthreads();
        }
    }

    #pragma unroll
    for (int mf = 0; mf < 2; mf++) {
        const int r0 = bm + m0 + mf * 16 + g;
        #pragma unroll
        for (int nf = 0; nf < 4; nf++) {
            const int col = bn + n0 + nf * 8 + 2 * t;
            const float b0 = bias[col], b1 = bias[col + 1];
            float2 o0, o1;
            o0.x = acc[mf][nf][0] + b0; o0.y = acc[mf][nf][1] + b1;
            o1.x = acc[mf][nf][2] + b0; o1.y = acc[mf][nf][3] + b1;
            if (do_relu) {
                o0.x = roundtf(fmaxf(o0.x, 0.f)); o0.y = roundtf(fmaxf(o0.y, 0.f));
                o1.x = roundtf(fmaxf(o1.x, 0.f)); o1.y = roundtf(fmaxf(o1.y, 0.f));
            }
            *(float2*)(C + (size_t)r0 * N + col)       = o0;
            *(float2*)(C + (size_t)(r0 + 8) * N + col) = o1;
        }
    }
}

// ============ chunked causal linear attention with fused FAVOR ============
#define CST 68   // smem tile stride (words)
#define OMS 33   // omega smem stride

__device__ __forceinline__ void load_tile(
    float* dst, const float* __restrict__ src, size_t gbase, int tid)
{
    const int t = tid >> 2;
    const int qo = (tid & 3) * 16;
    const float* p = src + gbase + (size_t)t * D_MODEL + qo;
    float* d = dst + t * CST + qo;
    #pragma unroll
    for (int i = 0; i < 4; i++)
        *(float4*)(d + i * 4) = *(const float4*)(p + i * 4);
}

__device__ __forceinline__ void favor_uh(
    const float* __restrict__ row, const float* __restrict__ om,
    int grp, float u[8], float& h)
{
    const float scale = 0.35355339059327373f;   // 64^-0.25
    #pragma unroll
    for (int jj = 0; jj < 8; jj++) u[jj] = 0.f;
    h = 0.f;
    #pragma unroll 4
    for (int d = 0; d < DH; d++) {
        const float xs = row[d] * scale;
        h = fmaf(xs, xs, h);
        const float* omd = om + d * OMS + grp * 8;
        #pragma unroll
        for (int jj = 0; jj < 8; jj++)
            u[jj] = fmaf(xs, omd[jj], u[jj]);
    }
    h *= 0.5f;
}

#define SUMS_SMEM ((3 * 64 * CST + 64 * OMS) * 4)
__global__ __launch_bounds__(256, 2) void chunk_sums_kernel(
    const float* __restrict__ Kraw, const float* __restrict__ V,
    const float* __restrict__ omega,
    float* __restrict__ gS, float* __restrict__ gZ)
{
    extern __shared__ float s1[];
    float* kr = s1;
    float* vs = s1 + 64 * CST;
    float* kf = s1 + 2 * 64 * CST;
    float* om = s1 + 3 * 64 * CST;

    const int ch = blockIdx.x;
    const int bh = blockIdx.y;
    const int tid = threadIdx.x;
    const int b = bh >> 4, hd = bh & 15;
    const size_t gbase = (size_t)b * 1024 * D_MODEL + (size_t)(ch * CLEN) * D_MODEL + hd * DH;

    load_tile(kr, Kraw, gbase, tid);
    load_tile(vs, V,  gbase, tid);
    for (int i = tid; i < DH * 32; i += 256)
        om[(i >> 5) * OMS + (i & 31)] = omega[i];
    __syncthreads();

    {
        const int tok = tid >> 2, grp = tid & 3;
        float u[8], h;
        favor_uh(kr + tok * CST, om, grp, u, h);
        float* kfr = kf + tok * CST + grp * 8;
        #pragma unroll
        for (int jj = 0; jj < 8; jj++) {
            kfr[jj]      = expf(u[jj]  - h) * 0.125f;
            kfr[32 + jj] = expf(-u[jj] - h) * 0.125f;
        }
    }
    __syncthreads();

    const int mg = (tid >> 4) * 4;
    const int dg = (tid & 15) * 4;

    float acc[4][4];
    float zz[4];
    #pragma unroll
    for (int e = 0; e < 4; e++) {
        zz[e] = 0.f;
        #pragma unroll
        for (int c = 0; c < 4; c++) acc[e][c] = 0.f;
    }

    #pragma unroll 4
    for (int t = 0; t < CLEN; t++) {
        float4 v4 = *(const float4*)(vs + t * CST + dg);
        #pragma unroll
        for (int e = 0; e < 4; e++) {
            const float kv = kf[t * CST + mg + e];
            zz[e] += kv;
            acc[e][0] = fmaf(kv, v4.x, acc[e][0]);
            acc[e][1] = fmaf(kv, v4.y, acc[e][1]);
            acc[e][2] = fmaf(kv, v4.z, acc[e][2]);
            acc[e][3] = fmaf(kv, v4.w, acc[e][3]);
        }
    }

    const size_t idx = (size_t)(bh * NCHUNK + ch);
    #pragma unroll
    for (int e = 0; e < 4; e++)
        *(float4*)(gS + idx * 4096 + (size_t)(mg + e) * 64 + dg) =
            make_float4(acc[e][0], acc[e][1], acc[e][2], acc[e][3]);
    if ((tid & 15) == 0) {
        #pragma unroll
        for (int e = 0; e < 4; e++) gZ[idx * 64 + mg + e] = zz[e];
    }
}

__global__ __launch_bounds__(256) void chunk_prefix_kernel(
    float* __restrict__ gS, float* __restrict__ gZ)
{
    const int gid = blockIdx.x * 256 + threadIdx.x;   // 0 .. 131071
    const int bh = gid >> 12;
    const int e  = gid & 4095;

    const size_t base = (size_t)bh * (NCHUNK * 4096) + e;
    float vals[NCHUNK];
    #pragma unroll
    for (int ch = 0; ch < NCHUNK; ch++)
        vals[ch] = gS[base + (size_t)ch * 4096];

    float run = 0.f;
    #pragma unroll
    for (int ch = 0; ch < NCHUNK; ch++) {
        const float t = vals[ch];
        gS[base + (size_t)ch * 4096] = run;
        run += t;
    }

    if (e < 64) {
        const size_t zbase = (size_t)bh * (NCHUNK * 64) + e;
        float zv[NCHUNK];
        #pragma unroll
        for (int ch = 0; ch < NCHUNK; ch++)
            zv[ch] = gZ[zbase + ch * 64];
        float zr = 0.f;
        #pragma unroll
        for (int ch = 0; ch < NCHUNK; ch++) {
            const float t = zv[ch];
            gZ[zbase + ch * 64] = zr;
            zr += t;
        }
    }
}

#define ATTN_SMEM ((5 * 64 * CST + 64 + 64 * OMS) * 4)
__global__ __launch_bounds__(256, 2) void chunk_attn_kernel(
    const float* __restrict__ Qraw, const float* __restrict__ Kraw,
    const float* __restrict__ V, const float* __restrict__ omega,
    const float* __restrict__ gS, const float* __restrict__ gZ,
    float* __restrict__ Out)
{
    extern __shared__ float smw[];
    float* qs = smw;
    float* kt = smw + 64 * CST;
    float* vs = smw + 2 * 64 * CST;
    float* Sp = smw + 3 * 64 * CST;
    float* Am = smw + 4 * 64 * CST;
    float* zp = smw + 5 * 64 * CST;
    float* om = smw + 5 * 64 * CST + 64;

    const int ch = blockIdx.x;
    const int bh = blockIdx.y;
    const int tid = threadIdx.x;
    const int b = bh >> 4, hd = bh & 15;
    const size_t gbase = (size_t)b * 1024 * D_MODEL + (size_t)(ch * CLEN) * D_MODEL + hd * DH;
    const size_t idx = (size_t)(bh * NCHUNK + ch);

    load_tile(qs, Qraw, gbase, tid);
    load_tile(Am, Kraw, gbase, tid);
    load_tile(vs, V,  gbase, tid);
    {
        const int m = tid >> 2;
        const int qo = (tid & 3) * 16;
        const float* p = gS + idx * 4096 + (size_t)m * 64 + qo;
        float* dp = Sp + m * CST + qo;
        #pragma unroll
        for (int i = 0; i < 4; i++)
            *(float4*)(dp + i * 4) = *(const float4*)(p + i * 4);
    }
    if (tid < 64) zp[tid] = gZ[idx * 64 + tid];
    for (int i = tid; i < DH * 32; i += 256)
        om[(i >> 5) * OMS + (i & 31)] = omega[i];
    __syncthreads();

    const int tok = tid >> 2, grp = tid & 3;
    float uq[8], hq, uk[8], hk;
    favor_uh(qs + tok * CST, om, grp, uq, hq);
    favor_uh(Am + tok * CST, om, grp, uk, hk);
    __syncthreads();

    {
        float* qfr = qs + tok * CST + grp * 8;
        #pragma unroll
        for (int jj = 0; jj < 8; jj++) {
            qfr[jj]      = expf(uq[jj]  - hq) * 0.125f;
            qfr[32 + jj] = expf(-uq[jj] - hq) * 0.125f;
        }
        const int jb = grp * 8;
        #pragma unroll
        for (int jj = 0; jj < 8; jj++) {
            kt[(jb + jj) * CST + tok]      = expf(uk[jj]  - hk) * 0.125f;
            kt[(32 + jb + jj) * CST + tok] = expf(-uk[jj] - hk) * 0.125f;
        }
    }
    __syncthreads();

    const int ig = (tid >> 4) * 4;
    const int jg = (tid & 15) * 4;

    float a[4][4];
    float qz[4];
    #pragma unroll
    for (int e = 0; e < 4; e++) {
        qz[e] = 0.f;
        #pragma unroll
        for (int c = 0; c < 4; c++) a[e][c] = 0.f;
    }
    #pragma unroll 4
    for (int m = 0; m < DH; m++) {
        const float zv = zp[m];
        float4 k4 = *(const float4*)(kt + m * CST + jg);
        #pragma unroll
        for (int e = 0; e < 4; e++) {
            const float qv = qs[(ig + e) * CST + m];
            qz[e] = fmaf(qv, zv, qz[e]);
            a[e][0] = fmaf(qv, k4.x, a[e][0]);
            a[e][1] = fmaf(qv, k4.y, a[e][1]);
            a[e][2] = fmaf(qv, k4.z, a[e][2]);
            a[e][3] = fmaf(qv, k4.w, a[e][3]);
        }
    }
    float den[4];
    #pragma unroll
    for (int e = 0; e < 4; e++) {
        const int i = ig + e;
        #pragma unroll
        for (int c = 0; c < 4; c++)
            if (jg + c > i) a[e][c] = 0.f;
        float rs = a[e][0] + a[e][1] + a[e][2] + a[e][3];
        rs += __shfl_xor_sync(0xffffffffu, rs, 1);
        rs += __shfl_xor_sync(0xffffffffu, rs, 2);
        rs += __shfl_xor_sync(0xffffffffu, rs, 4);
        rs += __shfl_xor_sync(0xffffffffu, rs, 8);
        den[e] = qz[e] + rs + 1e-6f;
        *(float4*)(Am + i * CST + jg) = make_float4(a[e][0], a[e][1], a[e][2], a[e][3]);
    }
    __syncthreads();

    float acc[4][4];
    #pragma unroll
    for (int e = 0; e < 4; e++)
        #pragma unroll
        for (int c = 0; c < 4; c++) acc[e][c] = 0.f;

    #pragma unroll 4
    for (int m = 0; m < DH; m++) {
        float4 s4 = *(const float4*)(Sp + m * CST + jg);
        #pragma unroll
        for (int e = 0; e < 4; e++) {
            const float qv = qs[(ig + e) * CST + m];
            acc[e][0] = fmaf(qv, s4.x, acc[e][0]);
            acc[e][1] = fmaf(qv, s4.y, acc[e][1]);
            acc[e][2] = fmaf(qv, s4.z, acc[e][2]);
            acc[e][3] = fmaf(qv, s4.w, acc[e][3]);
        }
    }
    const int jmax = ig + 3;
    for (int j = 0; j <= jmax; j++) {
        float4 v4 = *(const float4*)(vs + j * CST + jg);
        #pragma unroll
        for (int e = 0; e < 4; e++) {
            const float av = Am[(ig + e) * CST + j];
            acc[e][0] = fmaf(av, v4.x, acc[e][0]);
            acc[e][1] = fmaf(av, v4.y, acc[e][1]);
            acc[e][2] = fmaf(av, v4.z, acc[e][2]);
            acc[e][3] = fmaf(av, v4.w, acc[e][3]);
        }
    }

    #pragma unroll
    for (int e = 0; e < 4; e++) {
        const float inv = 1.f / den[e];
        float* op = Out + gbase + (size_t)(ig + e) * D_MODEL + jg;
        *(float4*)op = make_float4(roundtf(acc[e][0] * inv), roundtf(acc[e][1] * inv),
                                   roundtf(acc[e][2] * inv), roundtf(acc[e][3] * inv));
    }
}

// ---------------- LayerNorm: out = LN(a + r) * g + b ; optional rounded copy ----------------
__global__ __launch_bounds__(256) void ln_kernel(
    float* __restrict__ out, const float* __restrict__ a,
    const float* __restrict__ r, const float* __restrict__ gam,
    const float* __restrict__ bet, float* __restrict__ outr)
{
    const int row = blockIdx.x;
    const int tid = threadIdx.x;
    const float* pa = a + (size_t)row * D_MODEL;
    const float* pr = r + (size_t)row * D_MODEL;

    float v[4];
    float s = 0.f, ss = 0.f;
    #pragma unroll
    for (int i = 0; i < 4; i++) {
        int idx = tid + i * 256;
        float t = pa[idx] + pr[idx];
        v[i] = t; s += t; ss = fmaf(t, t, ss);
    }

    __shared__ float red[18];
    #pragma unroll
    for (int o = 16; o; o >>= 1) {
        s  += __shfl_xor_sync(0xffffffffu, s,  o);
        ss += __shfl_xor_sync(0xffffffffu, ss, o);
    }
    const int w = tid >> 5, lane = tid & 31;
    __shared__ float rw[16];
    if (lane == 0) { rw[w] = s; rw[w + 8] = ss; }
    __syncthreads();
    if (tid == 0) {
        float S0 = 0.f, S1 = 0.f;
        #pragma unroll
        for (int i = 0; i < 8; i++) { S0 += rw[i]; S1 += rw[i + 8]; }
        red[16] = S0; red[17] = S1;
    }
    __syncthreads();

    const float mean = red[16] * (1.f / 1024.f);
    const float var  = red[17] * (1.f / 1024.f) - mean * mean;
    const float inv  = rsqrtf(var + 1e-5f);

    float* po = out + (size_t)row * D_MODEL;
    float* pq = (outr != nullptr) ? outr + (size_t)row * D_MODEL : nullptr;
    #pragma unroll
    for (int i = 0; i < 4; i++) {
        int idx = tid + i * 256;
        float o = (v[i] - mean) * inv * gam[idx] + bet[idx];
        po[idx] = o;
        if (pq) pq[idx] = roundtf(o);
    }
}

// ---------------- launch ----------------
extern "C" void kernel_launch(void* const* d_in, const int* in_sizes, int n_in,
                              void* d_out, int out_size)
{
    const float* x    = (const float*)d_in[0];
    const float* Wq   = (const float*)d_in[1];
    const float* bq   = (const float*)d_in[2];
    const float* Wk   = (const float*)d_in[3];
    const float* bk   = (const float*)d_in[4];
    const float* Wv   = (const float*)d_in[5];
    const float* bv   = (const float*)d_in[6];
    const float* Wo   = (const float*)d_in[7];
    const float* bo   = (const float*)d_in[8];
    const float* omg  = (const float*)d_in[9];
    const float* ln1g = (const float*)d_in[10];
    const float* ln1b = (const float*)d_in[11];
    const float* ln2g = (const float*)d_in[12];
    const float* ln2b = (const float*)d_in[13];
    const float* W1   = (const float*)d_in[14];
    const float* bf1  = (const float*)d_in[15];
    const float* W2   = (const float*)d_in[16];
    const float* bf2  = (const float*)d_in[17];
    float* out = (float*)d_out;

    float *cur, *q, *k, *v, *h, *hr, *xr, *ffn, *gS, *gZ;
    cudaGetSymbolAddress((void**)&cur, g_cur);
    cudaGetSymbolAddress((void**)&q,   g_q);
    cudaGetSymbolAddress((void**)&k,   g_k);
    cudaGetSymbolAddress((void**)&v,   g_v);
    cudaGetSymbolAddress((void**)&h,   g_h);
    cudaGetSymbolAddress((void**)&hr,  g_hr);
    cudaGetSymbolAddress((void**)&xr,  g_xr);
    cudaGetSymbolAddress((void**)&ffn, g_ffn);
    cudaGetSymbolAddress((void**)&gS,  g_S);
    cudaGetSymbolAddress((void**)&gZ,  g_Z);

    cudaFuncSetAttribute(mma_gemm, cudaFuncAttributeMaxDynamicSharedMemorySize, GEMM_SMEM);
    cudaFuncSetAttribute(chunk_sums_kernel, cudaFuncAttributeMaxDynamicSharedMemorySize, SUMS_SMEM);
    cudaFuncSetAttribute(chunk_attn_kernel, cudaFuncAttributeMaxDynamicSharedMemorySize, ATTN_SMEM);

    // prep: tf32-round layer-0 activation
    const int nX4 = NTOK * D_MODEL / 4;
    round_kernel<<<nX4 / 256, 256>>>(x, xr, nX4);

    const dim3 gQKV(D_MODEL / 128, NTOK / 128, 3);
    const dim3 gD(D_MODEL / 128, NTOK / 128, 1);
    const dim3 gF(DFF_DIM / 128, NTOK / 128, 1);
    const dim3 gCh(NCHUNK, 32);
    const int  gPref = (32 * 4096) / 256;

    for (int l = 0; l < NLAYER; l++) {
        const size_t wDD  = (size_t)l * D_MODEL * D_MODEL;
        const size_t wDF  = (size_t)l * D_MODEL * DFF_DIM;
        const size_t bD   = (size_t)l * D_MODEL;
        const size_t bF   = (size_t)l * DFF_DIM;
        const size_t oOff = (size_t)l * DH * 32;
        const float* resA = (l == 0) ? x : cur;

        mma_gemm<<<gQKV, 512, GEMM_SMEM>>>(xr,
            Wq + wDD, Wk + wDD, Wv + wDD,
            bq + bD, bk + bD, bv + bD,
            q, k, v, NTOK, D_MODEL, D_MODEL, 0);

        chunk_sums_kernel<<<gCh, 256, SUMS_SMEM>>>(k, v, omg + oOff, gS, gZ);
        chunk_prefix_kernel<<<gPref, 256>>>(gS, gZ);
        chunk_attn_kernel<<<gCh, 256, ATTN_SMEM>>>(q, k, v, omg + oOff, gS, gZ, q);

        mma_gemm<<<gD, 512, GEMM_SMEM>>>(q,
            Wo + wDD, Wo + wDD, Wo + wDD,
            bo + bD, bo + bD, bo + bD,
            k, k, k, NTOK, D_MODEL, D_MODEL, 0);
        ln_kernel<<<NTOK, 256>>>(h, resA, k, ln1g + bD, ln1b + bD, hr);

        mma_gemm<<<gF, 512, GEMM_SMEM>>>(hr,
            W1 + wDF, W1 + wDF, W1 + wDF,
            bf1 + bF, bf1 + bF, bf1 + bF,
            ffn, ffn, ffn, NTOK, DFF_DIM, D_MODEL, 1);
        mma_gemm<<<gD, 512, GEMM_SMEM>>>(ffn,
            W2 + wDF, W2 + wDF, W2 + wDF,
            bf2 + bD, bf2 + bD, bf2 + bD,
            v, v, v, NTOK, D_MODEL, DFF_DIM, 0);

        const bool last = (l == NLAYER - 1);
        float* dst = last ? out : cur;
        ln_kernel<<<NTOK, 256>>>(dst, h, v, ln2g + bD, ln2b + bD, last ? nullptr : xr);
    }
}

// round 16
// speedup vs baseline: 1.1190x; 1.0043x over previous
#include <cuda_runtime.h>
#include <cstdint>
#include <math.h>

// ---------------- problem constants ----------------
#define D_MODEL 1024
#define DFF_DIM 4096
#define NTOK    2048          // B*S = 2*1024
#define NHEAD   16
#define DH      64
#define NLAYER  3
#define NCHUNK  16            // chunks per sequence
#define CLEN    64            // tokens per chunk

// ---------------- scratch (no allocs allowed) ----------------
__device__ float g_cur[NTOK * D_MODEL];
__device__ float g_q  [NTOK * D_MODEL];
__device__ float g_k  [NTOK * D_MODEL];
__device__ float g_v  [NTOK * D_MODEL];
__device__ float g_h  [NTOK * D_MODEL];
__device__ float g_hr [NTOK * D_MODEL];      // tf32-rounded h (FFN1 A operand)
__device__ float g_xr [NTOK * D_MODEL];      // tf32-rounded activation (QKV A operand)
__device__ float g_ffn[NTOK * DFF_DIM];
__device__ float g_S  [32 * NCHUNK * DH * DH];
__device__ float g_Z  [32 * NCHUNK * DH];

// ================= helpers =================
__device__ __forceinline__ uint32_t f2tf32(float f) {
    uint32_t u;
    asm("cvt.rna.tf32.f32 %0, %1;" : "=r"(u) : "f"(f));
    return u;
}
__device__ __forceinline__ float roundtf(float f) {
    return __uint_as_float(f2tf32(f));
}
__device__ __forceinline__ uint32_t smem_u32(const void* p) {
    uint32_t a;
    asm("{ .reg .u64 t; cvta.to.shared.u64 t, %1; cvt.u32.u64 %0, t; }" : "=r"(a) : "l"(p));
    return a;
}
__device__ __forceinline__ void mma_tf32(float c[4], uint32_t a0, uint32_t a1,
                                         uint32_t a2, uint32_t a3,
                                         uint32_t b0, uint32_t b1) {
    asm volatile(
        "mma.sync.aligned.m16n8k8.row.col.f32.tf32.tf32.f32 "
        "{%0,%1,%2,%3}, {%4,%5,%6,%7}, {%8,%9}, {%0,%1,%2,%3};"
        : "+f"(c[0]), "+f"(c[1]), "+f"(c[2]), "+f"(c[3])
        : "r"(a0), "r"(a1), "r"(a2), "r"(a3), "r"(b0), "r"(b1));
}
#define CP16(dst, src) \
    asm volatile("cp.async.cg.shared.global [%0], [%1], 16;" :: "r"(dst), "l"(src) : "memory")
#define CP_COMMIT() asm volatile("cp.async.commit_group;" ::: "memory")
#define CP_WAIT0()  asm volatile("cp.async.wait_group 0;" ::: "memory")

// ---------------- tf32 rounding copy (layer-0 x only) ----------------
__global__ void round_kernel(const float* __restrict__ src, float* __restrict__ dst, int n4)
{
    int i = blockIdx.x * blockDim.x + threadIdx.x;
    if (i < n4) {
        float4 v = ((const float4*)src)[i];
        uint4 u;
        u.x = f2tf32(v.x); u.y = f2tf32(v.y);
        u.z = f2tf32(v.z); u.w = f2tf32(v.w);
        ((uint4*)dst)[i] = u;
    }
}

// ================= TF32 tensor-core GEMM — fully-async staging =================
// A (activations, pre-rounded RNA): cp.async raw copy.
// B (weights): cp.async raw fp32 bits -> consumed as tf32 (RZ truncation by HW).
#define BK      64
#define ASTRIDE 68
#define BSTRIDE 168
#define ABUF (128 * ASTRIDE)
#define BBUF (64 * BSTRIDE)
#define GEMM_SMEM ((2 * ABUF + 2 * BBUF) * 4)

__global__ __launch_bounds__(512, 1) void mma_gemm(
    const float* __restrict__ A,
    const float* __restrict__ B0, const float* __restrict__ B1, const float* __restrict__ B2,
    const float* __restrict__ bias0, const float* __restrict__ bias1, const float* __restrict__ bias2,
    float* __restrict__ C0, float* __restrict__ C1, float* __restrict__ C2,
    int M, int N, int K, int do_relu)
{
    extern __shared__ float sm[];
    const uint32_t smb = smem_u32(sm);

    const int z = blockIdx.z;
    const float* B    = (z == 0) ? B0 : (z == 1) ? B1 : B2;
    const float* bias = (z == 0) ? bias0 : (z == 1) ? bias1 : bias2;
    float* C          = (z == 0) ? C0 : (z == 1) ? C1 : C2;

    const int tid  = threadIdx.x;
    const int bm   = blockIdx.y * 128;
    const int bn   = blockIdx.x * 128;
    const int lane = tid & 31;
    const int warp = tid >> 5;          // 0..15
    const int g    = lane >> 2;
    const int t    = lane & 3;
    const int m0   = (warp & 3) * 32;
    const int n0   = (warp >> 2) * 32;

    float acc[2][4][4];
    #pragma unroll
    for (int i = 0; i < 2; i++)
        #pragma unroll
        for (int j = 0; j < 4; j++)
            #pragma unroll
            for (int e = 0; e < 4; e++) acc[i][j][e] = 0.f;

    const int ar = tid >> 2;              // 0..127
    const int ac = (tid & 3) * 8;         // 0,8,16,24
    const int br = tid >> 4;              // 0..31
    const int bc = (tid & 15) * 8;        // 0..120
    const int bcp = bc + ((bc >> 5) << 2);

    const float* Abase = A + (size_t)(bm + ar) * K + ac;
    const float* Bbase = B + (size_t)br * N + bn + bc;
    const uint32_t aoff = 4u * (uint32_t)(ar * ASTRIDE + ac);
    const uint32_t boff = 4u * (uint32_t)(br * BSTRIDE + bcp);

    int cnp[4];
    #pragma unroll
    for (int nf = 0; nf < 4; nf++) {
        const int cb = n0 + nf * 8;
        cnp[nf] = cb + ((cb >> 5) << 2) + g;
    }

    const int NC = K / BK;

    // issue full chunk (A + B, both halves) into buffer `buf` via cp.async
    auto issue_chunk = [&](int buf, int k0) {
        #pragma unroll
        for (int half = 0; half < 2; half++) {
            const int koff = half * 32;
            const float* asrc = Abase + k0 + koff;
            uint32_t adst = smb + 4u * (uint32_t)(buf * ABUF) + aoff + 4u * (uint32_t)koff;
            CP16(adst, asrc);
            CP16(adst + 16u, asrc + 4);
            const float* bsrc = Bbase + (size_t)(k0 + koff) * N;
            uint32_t bdst = smb + 4u * (uint32_t)(2 * ABUF + buf * BBUF)
                          + boff + 4u * (uint32_t)(koff * BSTRIDE);
            CP16(bdst, bsrc);
            CP16(bdst + 16u, bsrc + 4);
        }
    };

    issue_chunk(0, 0);
    CP_COMMIT();
    CP_WAIT0();
    __syncthreads();

    for (int c = 0; c < NC; c++) {
        const int buf = c & 1;
        const bool more = (c + 1 < NC);
        if (more) {
            issue_chunk(buf ^ 1, (c + 1) * BK);
            CP_COMMIT();
        }

        const uint32_t* Au = (const uint32_t*)(sm + buf * ABUF);
        const uint32_t* Bu = (const uint32_t*)(sm + 2 * ABUF + buf * BBUF);

        #pragma unroll
        for (int ks = 0; ks < 8; ks++) {
            const int kk = ks * 8;
            uint32_t af[2][4];
            #pragma unroll
            for (int mf = 0; mf < 2; mf++) {
                const int r = m0 + mf * 16 + g;
                af[mf][0] = Au[r * ASTRIDE + kk + t];
                af[mf][1] = Au[(r + 8) * ASTRIDE + kk + t];
                af[mf][2] = Au[r * ASTRIDE + kk + t + 4];
                af[mf][3] = Au[(r + 8) * ASTRIDE + kk + t + 4];
            }
            #pragma unroll
            for (int nf = 0; nf < 4; nf++) {
                uint32_t b0 = Bu[(kk + t) * BSTRIDE + cnp[nf]];
                uint32_t b1 = Bu[(kk + t + 4) * BSTRIDE + cnp[nf]];
                #pragma unroll
                for (int mf = 0; mf < 2; mf++)
                    mma_tf32(acc[mf][nf], af[mf][0], af[mf][1], af[mf][2], af[mf][3], b0, b1);
            }
        }

        if (more) {
            CP_WAIT0();
            __syncthreads();
        }
    }

    #pragma unroll
    for (int mf = 0; mf < 2; mf++) {
        const int r0 = bm + m0 + mf * 16 + g;
        #pragma unroll
        for (int nf = 0; nf < 4; nf++) {
            const int col = bn + n0 + nf * 8 + 2 * t;
            const float b0 = bias[col], b1 = bias[col + 1];
            float2 o0, o1;
            o0.x = acc[mf][nf][0] + b0; o0.y = acc[mf][nf][1] + b1;
            o1.x = acc[mf][nf][2] + b0; o1.y = acc[mf][nf][3] + b1;
            if (do_relu) {
                o0.x = roundtf(fmaxf(o0.x, 0.f)); o0.y = roundtf(fmaxf(o0.y, 0.f));
                o1.x = roundtf(fmaxf(o1.x, 0.f)); o1.y = roundtf(fmaxf(o1.y, 0.f));
            }
            *(float2*)(C + (size_t)r0 * N + col)       = o0;
            *(float2*)(C + (size_t)(r0 + 8) * N + col) = o1;
        }
    }
}

// ============ chunked causal linear attention with fused FAVOR ============
#define CST 68   // smem tile stride (words)
#define OMS 33   // omega smem stride

__device__ __forceinline__ void load_tile(
    float* dst, const float* __restrict__ src, size_t gbase, int tid)
{
    const int t = tid >> 2;
    const int qo = (tid & 3) * 16;
    const float* p = src + gbase + (size_t)t * D_MODEL + qo;
    float* d = dst + t * CST + qo;
    #pragma unroll
    for (int i = 0; i < 4; i++)
        *(float4*)(d + i * 4) = *(const float4*)(p + i * 4);
}

__device__ __forceinline__ void favor_uh(
    const float* __restrict__ row, const float* __restrict__ om,
    int grp, float u[8], float& h)
{
    const float scale = 0.35355339059327373f;   // 64^-0.25
    #pragma unroll
    for (int jj = 0; jj < 8; jj++) u[jj] = 0.f;
    h = 0.f;
    #pragma unroll 4
    for (int d = 0; d < DH; d++) {
        const float xs = row[d] * scale;
        h = fmaf(xs, xs, h);
        const float* omd = om + d * OMS + grp * 8;
        #pragma unroll
        for (int jj = 0; jj < 8; jj++)
            u[jj] = fmaf(xs, omd[jj], u[jj]);
    }
    h *= 0.5f;
}

#define SUMS_SMEM ((3 * 64 * CST + 64 * OMS) * 4)
__global__ __launch_bounds__(256, 2) void chunk_sums_kernel(
    const float* __restrict__ Kraw, const float* __restrict__ V,
    const float* __restrict__ omega,
    float* __restrict__ gS, float* __restrict__ gZ)
{
    extern __shared__ float s1[];
    float* kr = s1;
    float* vs = s1 + 64 * CST;
    float* kf = s1 + 2 * 64 * CST;
    float* om = s1 + 3 * 64 * CST;

    const int ch = blockIdx.x;
    const int bh = blockIdx.y;
    const int tid = threadIdx.x;
    const int b = bh >> 4, hd = bh & 15;
    const size_t gbase = (size_t)b * 1024 * D_MODEL + (size_t)(ch * CLEN) * D_MODEL + hd * DH;

    load_tile(kr, Kraw, gbase, tid);
    load_tile(vs, V,  gbase, tid);
    for (int i = tid; i < DH * 32; i += 256)
        om[(i >> 5) * OMS + (i & 31)] = omega[i];
    __syncthreads();

    {
        const int tok = tid >> 2, grp = tid & 3;
        float u[8], h;
        favor_uh(kr + tok * CST, om, grp, u, h);
        float* kfr = kf + tok * CST + grp * 8;
        #pragma unroll
        for (int jj = 0; jj < 8; jj++) {
            kfr[jj]      = expf(u[jj]  - h) * 0.125f;
            kfr[32 + jj] = expf(-u[jj] - h) * 0.125f;
        }
    }
    __syncthreads();

    const int mg = (tid >> 4) * 4;
    const int dg = (tid & 15) * 4;

    float acc[4][4];
    float zz[4];
    #pragma unroll
    for (int e = 0; e < 4; e++) {
        zz[e] = 0.f;
        #pragma unroll
        for (int c = 0; c < 4; c++) acc[e][c] = 0.f;
    }

    #pragma unroll 4
    for (int t = 0; t < CLEN; t++) {
        float4 v4 = *(const float4*)(vs + t * CST + dg);
        #pragma unroll
        for (int e = 0; e < 4; e++) {
            const float kv = kf[t * CST + mg + e];
            zz[e] += kv;
            acc[e][0] = fmaf(kv, v4.x, acc[e][0]);
            acc[e][1] = fmaf(kv, v4.y, acc[e][1]);
            acc[e][2] = fmaf(kv, v4.z, acc[e][2]);
            acc[e][3] = fmaf(kv, v4.w, acc[e][3]);
        }
    }

    const size_t idx = (size_t)(bh * NCHUNK + ch);
    #pragma unroll
    for (int e = 0; e < 4; e++)
        *(float4*)(gS + idx * 4096 + (size_t)(mg + e) * 64 + dg) =
            make_float4(acc[e][0], acc[e][1], acc[e][2], acc[e][3]);
    if ((tid & 15) == 0) {
        #pragma unroll
        for (int e = 0; e < 4; e++) gZ[idx * 64 + mg + e] = zz[e];
    }
}

__global__ __launch_bounds__(256) void chunk_prefix_kernel(
    float* __restrict__ gS, float* __restrict__ gZ)
{
    const int gid = blockIdx.x * 256 + threadIdx.x;   // 0 .. 131071
    const int bh = gid >> 12;
    const int e  = gid & 4095;

    const size_t base = (size_t)bh * (NCHUNK * 4096) + e;
    float vals[NCHUNK];
    #pragma unroll
    for (int ch = 0; ch < NCHUNK; ch++)
        vals[ch] = gS[base + (size_t)ch * 4096];

    float run = 0.f;
    #pragma unroll
    for (int ch = 0; ch < NCHUNK; ch++) {
        const float t = vals[ch];
        gS[base + (size_t)ch * 4096] = run;
        run += t;
    }

    if (e < 64) {
        const size_t zbase = (size_t)bh * (NCHUNK * 64) + e;
        float zv[NCHUNK];
        #pragma unroll
        for (int ch = 0; ch < NCHUNK; ch++)
            zv[ch] = gZ[zbase + ch * 64];
        float zr = 0.f;
        #pragma unroll
        for (int ch = 0; ch < NCHUNK; ch++) {
            const float t = zv[ch];
            gZ[zbase + ch * 64] = zr;
            zr += t;
        }
    }
}

#define ATTN_SMEM ((5 * 64 * CST + 64 + 64 * OMS) * 4)
__global__ __launch_bounds__(256, 2) void chunk_attn_kernel(
    const float* __restrict__ Qraw, const float* __restrict__ Kraw,
    const float* __restrict__ V, const float* __restrict__ omega,
    const float* __restrict__ gS, const float* __restrict__ gZ,
    float* __restrict__ Out)
{
    extern __shared__ float smw[];
    float* qs = smw;
    float* kt = smw + 64 * CST;
    float* vs = smw + 2 * 64 * CST;
    float* Sp = smw + 3 * 64 * CST;
    float* Am = smw + 4 * 64 * CST;
    float* zp = smw + 5 * 64 * CST;
    float* om = smw + 5 * 64 * CST + 64;

    const int ch = blockIdx.x;
    const int bh = blockIdx.y;
    const int tid = threadIdx.x;
    const int b = bh >> 4, hd = bh & 15;
    const size_t gbase = (size_t)b * 1024 * D_MODEL + (size_t)(ch * CLEN) * D_MODEL + hd * DH;
    const size_t idx = (size_t)(bh * NCHUNK + ch);

    load_tile(qs, Qraw, gbase, tid);
    load_tile(Am, Kraw, gbase, tid);
    load_tile(vs, V,  gbase, tid);
    {
        const int m = tid >> 2;
        const int qo = (tid & 3) * 16;
        const float* p = gS + idx * 4096 + (size_t)m * 64 + qo;
        float* dp = Sp + m * CST + qo;
        #pragma unroll
        for (int i = 0; i < 4; i++)
            *(float4*)(dp + i * 4) = *(const float4*)(p + i * 4);
    }
    if (tid < 64) zp[tid] = gZ[idx * 64 + tid];
    for (int i = tid; i < DH * 32; i += 256)
        om[(i >> 5) * OMS + (i & 31)] = omega[i];
    __syncthreads();

    const int tok = tid >> 2, grp = tid & 3;
    float uq[8], hq, uk[8], hk;
    favor_uh(qs + tok * CST, om, grp, uq, hq);
    favor_uh(Am + tok * CST, om, grp, uk, hk);
    __syncthreads();

    {
        float* qfr = qs + tok * CST + grp * 8;
        #pragma unroll
        for (int jj = 0; jj < 8; jj++) {
            qfr[jj]      = expf(uq[jj]  - hq) * 0.125f;
            qfr[32 + jj] = expf(-uq[jj] - hq) * 0.125f;
        }
        const int jb = grp * 8;
        #pragma unroll
        for (int jj = 0; jj < 8; jj++) {
            kt[(jb + jj) * CST + tok]      = expf(uk[jj]  - hk) * 0.125f;
            kt[(32 + jb + jj) * CST + tok] = expf(-uk[jj] - hk) * 0.125f;
        }
    }
    __syncthreads();

    const int ig = (tid >> 4) * 4;
    const int jg = (tid & 15) * 4;

    float a[4][4];
    float qz[4];
    #pragma unroll
    for (int e = 0; e < 4; e++) {
        qz[e] = 0.f;
        #pragma unroll
        for (int c = 0; c < 4; c++) a[e][c] = 0.f;
    }
    #pragma unroll 4
    for (int m = 0; m < DH; m++) {
        const float zv = zp[m];
        float4 k4 = *(const float4*)(kt + m * CST + jg);
        #pragma unroll
        for (int e = 0; e < 4; e++) {
            const float qv = qs[(ig + e) * CST + m];
            qz[e] = fmaf(qv, zv, qz[e]);
            a[e][0] = fmaf(qv, k4.x, a[e][0]);
            a[e][1] = fmaf(qv, k4.y, a[e][1]);
            a[e][2] = fmaf(qv, k4.z, a[e][2]);
            a[e][3] = fmaf(qv, k4.w, a[e][3]);
        }
    }
    float den[4];
    #pragma unroll
    for (int e = 0; e < 4; e++) {
        const int i = ig + e;
        #pragma unroll
        for (int c = 0; c < 4; c++)
            if (jg + c > i) a[e][c] = 0.f;
        float rs = a[e][0] + a[e][1] + a[e][2] + a[e][3];
        rs += __shfl_xor_sync(0xffffffffu, rs, 1);
        rs += __shfl_xor_sync(0xffffffffu, rs, 2);
        rs += __shfl_xor_sync(0xffffffffu, rs, 4);
        rs += __shfl_xor_sync(0xffffffffu, rs, 8);
        den[e] = qz[e] + rs + 1e-6f;
        *(float4*)(Am + i * CST + jg) = make_float4(a[e][0], a[e][1], a[e][2], a[e][3]);
    }
    __syncthreads();

    float acc[4][4];
    #pragma unroll
    for (int e = 0; e < 4; e++)
        #pragma unroll
        for (int c = 0; c < 4; c++) acc[e][c] = 0.f;

    #pragma unroll 4
    for (int m = 0; m < DH; m++) {
        float4 s4 = *(const float4*)(Sp + m * CST + jg);
        #pragma unroll
        for (int e = 0; e < 4; e++) {
            const float qv = qs[(ig + e) * CST + m];
            acc[e][0] = fmaf(qv, s4.x, acc[e][0]);
            acc[e][1] = fmaf(qv, s4.y, acc[e][1]);
            acc[e][2] = fmaf(qv, s4.z, acc[e][2]);
            acc[e][3] = fmaf(qv, s4.w, acc[e][3]);
        }
    }
    const int jmax = ig + 3;
    for (int j = 0; j <= jmax; j++) {
        float4 v4 = *(const float4*)(vs + j * CST + jg);
        #pragma unroll
        for (int e = 0; e < 4; e++) {
            const float av = Am[(ig + e) * CST + j];
            acc[e][0] = fmaf(av, v4.x, acc[e][0]);
            acc[e][1] = fmaf(av, v4.y, acc[e][1]);
            acc[e][2] = fmaf(av, v4.z, acc[e][2]);
            acc[e][3] = fmaf(av, v4.w, acc[e][3]);
        }
    }

    #pragma unroll
    for (int e = 0; e < 4; e++) {
        const float inv = 1.f / den[e];
        float* op = Out + gbase + (size_t)(ig + e) * D_MODEL + jg;
        *(float4*)op = make_float4(roundtf(acc[e][0] * inv), roundtf(acc[e][1] * inv),
                                   roundtf(acc[e][2] * inv), roundtf(acc[e][3] * inv));
    }
}

// ---------------- LayerNorm: out = LN(a + r) * g + b ; optional rounded copy ----------------
__global__ __launch_bounds__(256) void ln_kernel(
    float* __restrict__ out, const float* __restrict__ a,
    const float* __restrict__ r, const float* __restrict__ gam,
    const float* __restrict__ bet, float* __restrict__ outr)
{
    const int row = blockIdx.x;
    const int tid = threadIdx.x;
    const float* pa = a + (size_t)row * D_MODEL;
    const float* pr = r + (size_t)row * D_MODEL;

    float v[4];
    float s = 0.f, ss = 0.f;
    #pragma unroll
    for (int i = 0; i < 4; i++) {
        int idx = tid + i * 256;
        float t = pa[idx] + pr[idx];
        v[i] = t; s += t; ss = fmaf(t, t, ss);
    }

    __shared__ float red[18];
    #pragma unroll
    for (int o = 16; o; o >>= 1) {
        s  += __shfl_xor_sync(0xffffffffu, s,  o);
        ss += __shfl_xor_sync(0xffffffffu, ss, o);
    }
    const int w = tid >> 5, lane = tid & 31;
    __shared__ float rw[16];
    if (lane == 0) { rw[w] = s; rw[w + 8] = ss; }
    __syncthreads();
    if (tid == 0) {
        float S0 = 0.f, S1 = 0.f;
        #pragma unroll
        for (int i = 0; i < 8; i++) { S0 += rw[i]; S1 += rw[i + 8]; }
        red[16] = S0; red[17] = S1;
    }
    __syncthreads();

    const float mean = red[16] * (1.f / 1024.f);
    const float var  = red[17] * (1.f / 1024.f) - mean * mean;
    const float inv  = rsqrtf(var + 1e-5f);

    float* po = out + (size_t)row * D_MODEL;
    float* pq = (outr != nullptr) ? outr + (size_t)row * D_MODEL : nullptr;
    #pragma unroll
    for (int i = 0; i < 4; i++) {
        int idx = tid + i * 256;
        float o = (v[i] - mean) * inv * gam[idx] + bet[idx];
        po[idx] = o;
        if (pq) pq[idx] = roundtf(o);
    }
}

// ---------------- launch ----------------
extern "C" void kernel_launch(void* const* d_in, const int* in_sizes, int n_in,
                              void* d_out, int out_size)
{
    const float* x    = (const float*)d_in[0];
    const float* Wq   = (const float*)d_in[1];
    const float* bq   = (const float*)d_in[2];
    const float* Wk   = (const float*)d_in[3];
    const float* bk   = (const float*)d_in[4];
    const float* Wv   = (const float*)d_in[5];
    const float* bv   = (const float*)d_in[6];
    const float* Wo   = (const float*)d_in[7];
    const float* bo   = (const float*)d_in[8];
    const float* omg  = (const float*)d_in[9];
    const float* ln1g = (const float*)d_in[10];
    const float* ln1b = (const float*)d_in[11];
    const float* ln2g = (const float*)d_in[12];
    const float* ln2b = (const float*)d_in[13];
    const float* W1   = (const float*)d_in[14];
    const float* bf1  = (const float*)d_in[15];
    const float* W2   = (const float*)d_in[16];
    const float* bf2  = (const float*)d_in[17];
    float* out = (float*)d_out;

    float *cur, *q, *k, *v, *h, *hr, *xr, *ffn, *gS, *gZ;
    cudaGetSymbolAddress((void**)&cur, g_cur);
    cudaGetSymbolAddress((void**)&q,   g_q);
    cudaGetSymbolAddress((void**)&k,   g_k);
    cudaGetSymbolAddress((void**)&v,   g_v);
    cudaGetSymbolAddress((void**)&h,   g_h);
    cudaGetSymbolAddress((void**)&hr,  g_hr);
    cudaGetSymbolAddress((void**)&xr,  g_xr);
    cudaGetSymbolAddress((void**)&ffn, g_ffn);
    cudaGetSymbolAddress((void**)&gS,  g_S);
    cudaGetSymbolAddress((void**)&gZ,  g_Z);

    cudaFuncSetAttribute(mma_gemm, cudaFuncAttributeMaxDynamicSharedMemorySize, GEMM_SMEM);
    cudaFuncSetAttribute(chunk_sums_kernel, cudaFuncAttributeMaxDynamicSharedMemorySize, SUMS_SMEM);
    cudaFuncSetAttribute(chunk_attn_kernel, cudaFuncAttributeMaxDynamicSharedMemorySize, ATTN_SMEM);

    // prep: tf32-round layer-0 activation
    const int nX4 = NTOK * D_MODEL / 4;
    round_kernel<<<nX4 / 256, 256>>>(x, xr, nX4);

    const dim3 gQKV(D_MODEL / 128, NTOK / 128, 3);
    const dim3 gD(D_MODEL / 128, NTOK / 128, 1);
    const dim3 gF(DFF_DIM / 128, NTOK / 128, 1);
    const dim3 gCh(NCHUNK, 32);
    const int  gPref = (32 * 4096) / 256;

    for (int l = 0; l < NLAYER; l++) {
        const size_t wDD  = (size_t)l * D_MODEL * D_MODEL;
        const size_t wDF  = (size_t)l * D_MODEL * DFF_DIM;
        const size_t bD   = (size_t)l * D_MODEL;
        const size_t bF   = (size_t)l * DFF_DIM;
        const size_t oOff = (size_t)l * DH * 32;
        const float* resA = (l == 0) ? x : cur;

        mma_gemm<<<gQKV, 512, GEMM_SMEM>>>(xr,
            Wq + wDD, Wk + wDD, Wv + wDD,
            bq + bD, bk + bD, bv + bD,
            q, k, v, NTOK, D_MODEL, D_MODEL, 0);

        chunk_sums_kernel<<<gCh, 256, SUMS_SMEM>>>(k, v, omg + oOff, gS, gZ);
        chunk_prefix_kernel<<<gPref, 256>>>(gS, gZ);
        chunk_attn_kernel<<<gCh, 256, ATTN_SMEM>>>(q, k, v, omg + oOff, gS, gZ, q);

        mma_gemm<<<gD, 512, GEMM_SMEM>>>(q,
            Wo + wDD, Wo + wDD, Wo + wDD,
            bo + bD, bo + bD, bo + bD,
            k, k, k, NTOK, D_MODEL, D_MODEL, 0);
        ln_kernel<<<NTOK, 256>>>(h, resA, k, ln1g + bD, ln1b + bD, hr);

        mma_gemm<<<gF, 512, GEMM_SMEM>>>(hr,
            W1 + wDF, W1 + wDF, W1 + wDF,
            bf1 + bF, bf1 + bF, bf1 + bF,
            ffn, ffn, ffn, NTOK, DFF_DIM, D_MODEL, 1);
        mma_gemm<<<gD, 512, GEMM_SMEM>>>(ffn,
            W2 + wDF, W2 + wDF, W2 + wDF,
            bf2 + bD, bf2 + bD, bf2 + bD,
            v, v, v, NTOK, D_MODEL, DFF_DIM, 0);

        const bool last = (l == NLAYER - 1);
        float* dst = last ? out : cur;
        ln_kernel<<<NTOK, 256>>>(dst, h, v, ln2g + bD, ln2b + bD, last ? nullptr : xr);
    }
}

// round 17
// speedup vs baseline: 1.5920x; 1.4227x over previous
#include <cuda_runtime.h>
#include <cuda_fp16.h>
#include <cstdint>
#include <math.h>

// ---------------- problem constants ----------------
#define D_MODEL 1024
#define DFF_DIM 4096
#define NTOK    2048          // B*S = 2*1024
#define NHEAD   16
#define DH      64
#define NLAYER  3
#define NCHUNK  16            // chunks per sequence
#define CLEN    64            // tokens per chunk

// ---------------- scratch (no allocs allowed) ----------------
__device__ float  g_cur[NTOK * D_MODEL];
__device__ float  g_q  [NTOK * D_MODEL];
__device__ float  g_k  [NTOK * D_MODEL];
__device__ float  g_v  [NTOK * D_MODEL];
__device__ float  g_h  [NTOK * D_MODEL];
__device__ float  g_S  [32 * NCHUNK * DH * DH];
__device__ float  g_Z  [32 * NCHUNK * DH];
__device__ __half g_xh [NTOK * D_MODEL];     // fp16 activation (QKV A operand)
__device__ __half g_hh [NTOK * D_MODEL];     // fp16 h (FFN1 A operand)
__device__ __half g_ah [NTOK * D_MODEL];     // fp16 attn out (Wo A operand)
__device__ __half g_fh [NTOK * DFF_DIM];     // fp16 ffn1 out (FFN2 A operand)

// ================= helpers =================
__device__ __forceinline__ uint32_t smem_u32(const void* p) {
    uint32_t a;
    asm("{ .reg .u64 t; cvta.to.shared.u64 t, %1; cvt.u32.u64 %0, t; }" : "=r"(a) : "l"(p));
    return a;
}
__device__ __forceinline__ void mma_f16(float c[4], uint32_t a0, uint32_t a1,
                                        uint32_t a2, uint32_t a3,
                                        uint32_t b0, uint32_t b1) {
    asm volatile(
        "mma.sync.aligned.m16n8k16.row.col.f32.f16.f16.f32 "
        "{%0,%1,%2,%3}, {%4,%5,%6,%7}, {%8,%9}, {%0,%1,%2,%3};"
        : "+f"(c[0]), "+f"(c[1]), "+f"(c[2]), "+f"(c[3])
        : "r"(a0), "r"(a1), "r"(a2), "r"(a3), "r"(b0), "r"(b1));
}
#define CP16(dst, src) \
    asm volatile("cp.async.cg.shared.global [%0], [%1], 16;" :: "r"(dst), "l"(src) : "memory")
#define CP_COMMIT() asm volatile("cp.async.commit_group;" ::: "memory")
#define CP_WAIT0()  asm volatile("cp.async.wait_group 0;" ::: "memory")

// ---------------- fp16 conversion copy (layer-0 x only) ----------------
__global__ void half_kernel(const float* __restrict__ src, __half* __restrict__ dst, int n4)
{
    int i = blockIdx.x * blockDim.x + threadIdx.x;
    if (i < n4) {
        float4 v = ((const float4*)src)[i];
        ((__half2*)dst)[2 * i]     = __floats2half2_rn(v.x, v.y);
        ((__half2*)dst)[2 * i + 1] = __floats2half2_rn(v.z, v.w);
    }
}

// ================= FP16 tensor-core GEMM =================
// C[M,N] = A[M,K](fp16) @ B[K,N](fp32->fp16 RNE) + bias.
// 128x128 tile, BK=64 halves, 512 threads, warp tile 32x32, m16n8k16.
// A smem: [m][k-half2], stride LDA=36 words. cp.async staged.
// B smem: [n][k-half2], stride LDB=36 words, column XOR-swizzled by (n>>3).
#define BKH  64
#define LDA  36
#define LDB  36
#define ABUF_H (128 * LDA)            // 4608 words
#define BBUF_H (128 * LDB)            // 4608 words
#define GEMM_SMEM ((2 * ABUF_H + 2 * BBUF_H) * 4)   // 73728 bytes

__global__ __launch_bounds__(512, 1) void mma_gemm_h(
    const __half* __restrict__ A,
    const float* __restrict__ B0, const float* __restrict__ B1, const float* __restrict__ B2,
    const float* __restrict__ bias0, const float* __restrict__ bias1, const float* __restrict__ bias2,
    float* __restrict__ Cf0, float* __restrict__ Cf1, float* __restrict__ Cf2,
    __half* __restrict__ Ch0, __half* __restrict__ Ch1, __half* __restrict__ Ch2,
    int M, int N, int K, int do_relu)
{
    extern __shared__ float sm[];
    uint32_t* smw = (uint32_t*)sm;
    const uint32_t smb = smem_u32(sm);

    const int z = blockIdx.z;
    const float* B    = (z == 0) ? B0 : (z == 1) ? B1 : B2;
    const float* bias = (z == 0) ? bias0 : (z == 1) ? bias1 : bias2;
    float*  Cf        = (z == 0) ? Cf0 : (z == 1) ? Cf1 : Cf2;
    __half* Ch        = (z == 0) ? Ch0 : (z == 1) ? Ch1 : Ch2;

    const int tid  = threadIdx.x;
    const int bm   = blockIdx.y * 128;
    const int bn   = blockIdx.x * 128;
    const int lane = tid & 31;
    const int warp = tid >> 5;          // 0..15
    const int g    = lane >> 2;
    const int t    = lane & 3;
    const int m0   = (warp & 3) * 32;
    const int n0   = (warp >> 2) * 32;

    float acc[2][4][4];
    #pragma unroll
    for (int i = 0; i < 2; i++)
        #pragma unroll
        for (int j = 0; j < 4; j++)
            #pragma unroll
            for (int e = 0; e < 4; e++) acc[i][j][e] = 0.f;

    // A staging: thread -> (row ar, quarter aq): 16 halves = 2 cp.async
    const int ar = tid >> 2;              // 0..127
    const int aq = tid & 3;               // 0..3
    // B staging: thread -> (k-pair kp, n-octet nq): 2k x 8n block
    const int kp = tid >> 4;              // 0..31
    const int nq = tid & 15;              // 0..15

    const __half* Abase = A + (size_t)(bm + ar) * K + aq * 16;
    const uint32_t aoffB = (uint32_t)(ar * LDA) * 4u + (uint32_t)aq * 32u;  // bytes

    // per-nf B read precompute
    int nArr[4], sArr[4];
    #pragma unroll
    for (int nf = 0; nf < 4; nf++) {
        nArr[nf] = n0 + nf * 8 + g;
        sArr[nf] = nArr[nf] >> 3;
    }

    const int NC = K / BKH;

    // A: issue chunk k0 (in halves) into buffer buf
    auto issueA = [&](int buf, int k0) {
        const __half* asrc = Abase + k0;
        uint32_t adst = smb + (uint32_t)(buf * ABUF_H) * 4u + aoffB;
        CP16(adst, asrc);
        CP16(adst + 16u, asrc + 8);
    };
    // B: load 2 rows x 8 cols fp32
    float4 f0a, f0b, f1a, f1b;
    auto ldgB = [&](int k0) {
        const float* p0 = B + (size_t)(k0 + 2 * kp) * N + bn + nq * 8;
        f0a = *(const float4*)(p0);
        f0b = *(const float4*)(p0 + 4);
        const float* p1 = p0 + N;
        f1a = *(const float4*)(p1);
        f1b = *(const float4*)(p1 + 4);
    };
    // B: cvt + STS (transpose pack: half2 = {row k, row k+1})
    auto stsB = [&](int buf) {
        const uint32_t cs = (uint32_t)(kp ^ nq);
        const uint32_t basew = (uint32_t)(2 * ABUF_H + buf * BBUF_H + (nq * 8) * LDB) + cs;
        const float* a0 = (const float*)&f0a;
        const float* a1 = (const float*)&f1a;
        #pragma unroll
        for (int i = 0; i < 4; i++)
            *(__half2*)(sm + basew + i * LDB) = __floats2half2_rn(a0[i], a1[i]);
        const float* b0p = (const float*)&f0b;
        const float* b1p = (const float*)&f1b;
        #pragma unroll
        for (int i = 0; i < 4; i++)
            *(__half2*)(sm + basew + (4 + i) * LDB) = __floats2half2_rn(b0p[i], b1p[i]);
    };

    // ---- prologue: chunk 0 ----
    issueA(0, 0);
    CP_COMMIT();
    ldgB(0);
    stsB(0);
    CP_WAIT0();
    __syncthreads();

    for (int c = 0; c < NC; c++) {
        const int buf = c & 1;
        const int nb  = buf ^ 1;
        const bool more = (c + 1 < NC);

        if (more) {
            issueA(nb, (c + 1) * BKH);
            CP_COMMIT();
            ldgB((c + 1) * BKH);
        }

        const uint32_t* Au = smw + buf * ABUF_H;
        const uint32_t* Bu = smw + 2 * ABUF_H + buf * BBUF_H;

        // ---- MMA half 1 (ks 0..1) ----
        #pragma unroll
        for (int ks = 0; ks < 2; ks++) {
            const int kk = ks * 8;
            uint32_t af[2][4];
            #pragma unroll
            for (int mf = 0; mf < 2; mf++) {
                const int r = m0 + mf * 16 + g;
                af[mf][0] = Au[r * LDA + kk + t];
                af[mf][1] = Au[(r + 8) * LDA + kk + t];
                af[mf][2] = Au[r * LDA + kk + t + 4];
                af[mf][3] = Au[(r + 8) * LDA + kk + t + 4];
            }
            #pragma unroll
            for (int nf = 0; nf < 4; nf++) {
                const int rowb = nArr[nf] * LDB;
                uint32_t b0 = Bu[rowb + ((kk + t) ^ sArr[nf])];
                uint32_t b1 = Bu[rowb + ((kk + t + 4) ^ sArr[nf])];
                #pragma unroll
                for (int mf = 0; mf < 2; mf++)
                    mma_f16(acc[mf][nf], af[mf][0], af[mf][1], af[mf][2], af[mf][3], b0, b1);
            }
        }

        if (more) stsB(nb);

        // ---- MMA half 2 (ks 2..3) ----
        #pragma unroll
        for (int ks = 2; ks < 4; ks++) {
            const int kk = ks * 8;
            uint32_t af[2][4];
            #pragma unroll
            for (int mf = 0; mf < 2; mf++) {
                const int r = m0 + mf * 16 + g;
                af[mf][0] = Au[r * LDA + kk + t];
                af[mf][1] = Au[(r + 8) * LDA + kk + t];
                af[mf][2] = Au[r * LDA + kk + t + 4];
                af[mf][3] = Au[(r + 8) * LDA + kk + t + 4];
            }
            #pragma unroll
            for (int nf = 0; nf < 4; nf++) {
                const int rowb = nArr[nf] * LDB;
                uint32_t b0 = Bu[rowb + ((kk + t) ^ sArr[nf])];
                uint32_t b1 = Bu[rowb + ((kk + t + 4) ^ sArr[nf])];
                #pragma unroll
                for (int mf = 0; mf < 2; mf++)
                    mma_f16(acc[mf][nf], af[mf][0], af[mf][1], af[mf][2], af[mf][3], b0, b1);
            }
        }

        if (more) {
            CP_WAIT0();
            __syncthreads();
        }
    }

    // ---- epilogue ----
    #pragma unroll
    for (int mf = 0; mf < 2; mf++) {
        const int r0 = bm + m0 + mf * 16 + g;
        #pragma unroll
        for (int nf = 0; nf < 4; nf++) {
            const int col = bn + n0 + nf * 8 + 2 * t;
            const float b0 = bias[col], b1 = bias[col + 1];
            float2 o0, o1;
            o0.x = acc[mf][nf][0] + b0; o0.y = acc[mf][nf][1] + b1;
            o1.x = acc[mf][nf][2] + b0; o1.y = acc[mf][nf][3] + b1;
            if (do_relu) {
                o0.x = fmaxf(o0.x, 0.f); o0.y = fmaxf(o0.y, 0.f);
                o1.x = fmaxf(o1.x, 0.f); o1.y = fmaxf(o1.y, 0.f);
            }
            if (Cf) {
                *(float2*)(Cf + (size_t)r0 * N + col)       = o0;
                *(float2*)(Cf + (size_t)(r0 + 8) * N + col) = o1;
            }
            if (Ch) {
                *(__half2*)(Ch + (size_t)r0 * N + col)       = __floats2half2_rn(o0.x, o0.y);
                *(__half2*)(Ch + (size_t)(r0 + 8) * N + col) = __floats2half2_rn(o1.x, o1.y);
            }
        }
    }
}

// ============ chunked causal linear attention with fused FAVOR ============
#define CST 68   // smem tile stride (words)
#define OMS 33   // omega smem stride

__device__ __forceinline__ void load_tile(
    float* dst, const float* __restrict__ src, size_t gbase, int tid)
{
    const int t = tid >> 2;
    const int qo = (tid & 3) * 16;
    const float* p = src + gbase + (size_t)t * D_MODEL + qo;
    float* d = dst + t * CST + qo;
    #pragma unroll
    for (int i = 0; i < 4; i++)
        *(float4*)(d + i * 4) = *(const float4*)(p + i * 4);
}

__device__ __forceinline__ void favor_uh(
    const float* __restrict__ row, const float* __restrict__ om,
    int grp, float u[8], float& h)
{
    const float scale = 0.35355339059327373f;   // 64^-0.25
    #pragma unroll
    for (int jj = 0; jj < 8; jj++) u[jj] = 0.f;
    h = 0.f;
    #pragma unroll 4
    for (int d = 0; d < DH; d++) {
        const float xs = row[d] * scale;
        h = fmaf(xs, xs, h);
        const float* omd = om + d * OMS + grp * 8;
        #pragma unroll
        for (int jj = 0; jj < 8; jj++)
            u[jj] = fmaf(xs, omd[jj], u[jj]);
    }
    h *= 0.5f;
}

#define SUMS_SMEM ((3 * 64 * CST + 64 * OMS) * 4)
__global__ __launch_bounds__(256, 2) void chunk_sums_kernel(
    const float* __restrict__ Kraw, const float* __restrict__ V,
    const float* __restrict__ omega,
    float* __restrict__ gS, float* __restrict__ gZ)
{
    extern __shared__ float s1[];
    float* kr = s1;
    float* vs = s1 + 64 * CST;
    float* kf = s1 + 2 * 64 * CST;
    float* om = s1 + 3 * 64 * CST;

    const int ch = blockIdx.x;
    const int bh = blockIdx.y;
    const int tid = threadIdx.x;
    const int b = bh >> 4, hd = bh & 15;
    const size_t gbase = (size_t)b * 1024 * D_MODEL + (size_t)(ch * CLEN) * D_MODEL + hd * DH;

    load_tile(kr, Kraw, gbase, tid);
    load_tile(vs, V,  gbase, tid);
    for (int i = tid; i < DH * 32; i += 256)
        om[(i >> 5) * OMS + (i & 31)] = omega[i];
    __syncthreads();

    {
        const int tok = tid >> 2, grp = tid & 3;
        float u[8], h;
        favor_uh(kr + tok * CST, om, grp, u, h);
        float* kfr = kf + tok * CST + grp * 8;
        #pragma unroll
        for (int jj = 0; jj < 8; jj++) {
            kfr[jj]      = expf(u[jj]  - h) * 0.125f;
            kfr[32 + jj] = expf(-u[jj] - h) * 0.125f;
        }
    }
    __syncthreads();

    const int mg = (tid >> 4) * 4;
    const int dg = (tid & 15) * 4;

    float acc[4][4];
    float zz[4];
    #pragma unroll
    for (int e = 0; e < 4; e++) {
        zz[e] = 0.f;
        #pragma unroll
        for (int c = 0; c < 4; c++) acc[e][c] = 0.f;
    }

    #pragma unroll 4
    for (int t = 0; t < CLEN; t++) {
        float4 v4 = *(const float4*)(vs + t * CST + dg);
        #pragma unroll
        for (int e = 0; e < 4; e++) {
            const float kv = kf[t * CST + mg + e];
            zz[e] += kv;
            acc[e][0] = fmaf(kv, v4.x, acc[e][0]);
            acc[e][1] = fmaf(kv, v4.y, acc[e][1]);
            acc[e][2] = fmaf(kv, v4.z, acc[e][2]);
            acc[e][3] = fmaf(kv, v4.w, acc[e][3]);
        }
    }

    const size_t idx = (size_t)(bh * NCHUNK + ch);
    #pragma unroll
    for (int e = 0; e < 4; e++)
        *(float4*)(gS + idx * 4096 + (size_t)(mg + e) * 64 + dg) =
            make_float4(acc[e][0], acc[e][1], acc[e][2], acc[e][3]);
    if ((tid & 15) == 0) {
        #pragma unroll
        for (int e = 0; e < 4; e++) gZ[idx * 64 + mg + e] = zz[e];
    }
}

__global__ __launch_bounds__(256) void chunk_prefix_kernel(
    float* __restrict__ gS, float* __restrict__ gZ)
{
    const int gid = blockIdx.x * 256 + threadIdx.x;   // 0 .. 131071
    const int bh = gid >> 12;
    const int e  = gid & 4095;

    const size_t base = (size_t)bh * (NCHUNK * 4096) + e;
    float vals[NCHUNK];
    #pragma unroll
    for (int ch = 0; ch < NCHUNK; ch++)
        vals[ch] = gS[base + (size_t)ch * 4096];

    float run = 0.f;
    #pragma unroll
    for (int ch = 0; ch < NCHUNK; ch++) {
        const float t = vals[ch];
        gS[base + (size_t)ch * 4096] = run;
        run += t;
    }

    if (e < 64) {
        const size_t zbase = (size_t)bh * (NCHUNK * 64) + e;
        float zv[NCHUNK];
        #pragma unroll
        for (int ch = 0; ch < NCHUNK; ch++)
            zv[ch] = gZ[zbase + ch * 64];
        float zr = 0.f;
        #pragma unroll
        for (int ch = 0; ch < NCHUNK; ch++) {
            const float t = zv[ch];
            gZ[zbase + ch * 64] = zr;
            zr += t;
        }
    }
}

#define ATTN_SMEM ((5 * 64 * CST + 64 + 64 * OMS) * 4)
__global__ __launch_bounds__(256, 2) void chunk_attn_kernel(
    const float* __restrict__ Qraw, const float* __restrict__ Kraw,
    const float* __restrict__ V, const float* __restrict__ omega,
    const float* __restrict__ gS, const float* __restrict__ gZ,
    __half* __restrict__ Outh)
{
    extern __shared__ float smw2[];
    float* qs = smw2;
    float* kt = smw2 + 64 * CST;
    float* vs = smw2 + 2 * 64 * CST;
    float* Sp = smw2 + 3 * 64 * CST;
    float* Am = smw2 + 4 * 64 * CST;
    float* zp = smw2 + 5 * 64 * CST;
    float* om = smw2 + 5 * 64 * CST + 64;

    const int ch = blockIdx.x;
    const int bh = blockIdx.y;
    const int tid = threadIdx.x;
    const int b = bh >> 4, hd = bh & 15;
    const size_t gbase = (size_t)b * 1024 * D_MODEL + (size_t)(ch * CLEN) * D_MODEL + hd * DH;
    const size_t idx = (size_t)(bh * NCHUNK + ch);

    load_tile(qs, Qraw, gbase, tid);
    load_tile(Am, Kraw, gbase, tid);
    load_tile(vs, V,  gbase, tid);
    {
        const int m = tid >> 2;
        const int qo = (tid & 3) * 16;
        const float* p = gS + idx * 4096 + (size_t)m * 64 + qo;
        float* dp = Sp + m * CST + qo;
        #pragma unroll
        for (int i = 0; i < 4; i++)
            *(float4*)(dp + i * 4) = *(const float4*)(p + i * 4);
    }
    if (tid < 64) zp[tid] = gZ[idx * 64 + tid];
    for (int i = tid; i < DH * 32; i += 256)
        om[(i >> 5) * OMS + (i & 31)] = omega[i];
    __syncthreads();

    const int tok = tid >> 2, grp = tid & 3;
    float uq[8], hq, uk[8], hk;
    favor_uh(qs + tok * CST, om, grp, uq, hq);
    favor_uh(Am + tok * CST, om, grp, uk, hk);
    __syncthreads();

    {
        float* qfr = qs + tok * CST + grp * 8;
        #pragma unroll
        for (int jj = 0; jj < 8; jj++) {
            qfr[jj]      = expf(uq[jj]  - hq) * 0.125f;
            qfr[32 + jj] = expf(-uq[jj] - hq) * 0.125f;
        }
        const int jb = grp * 8;
        #pragma unroll
        for (int jj = 0; jj < 8; jj++) {
            kt[(jb + jj) * CST + tok]      = expf(uk[jj]  - hk) * 0.125f;
            kt[(32 + jb + jj) * CST + tok] = expf(-uk[jj] - hk) * 0.125f;
        }
    }
    __syncthreads();

    const int ig = (tid >> 4) * 4;
    const int jg = (tid & 15) * 4;

    float a[4][4];
    float qz[4];
    #pragma unroll
    for (int e = 0; e < 4; e++) {
        qz[e] = 0.f;
        #pragma unroll
        for (int c = 0; c < 4; c++) a[e][c] = 0.f;
    }
    #pragma unroll 4
    for (int m = 0; m < DH; m++) {
        const float zv = zp[m];
        float4 k4 = *(const float4*)(kt + m * CST + jg);
        #pragma unroll
        for (int e = 0; e < 4; e++) {
            const float qv = qs[(ig + e) * CST + m];
            qz[e] = fmaf(qv, zv, qz[e]);
            a[e][0] = fmaf(qv, k4.x, a[e][0]);
            a[e][1] = fmaf(qv, k4.y, a[e][1]);
            a[e][2] = fmaf(qv, k4.z, a[e][2]);
            a[e][3] = fmaf(qv, k4.w, a[e][3]);
        }
    }
    float den[4];
    #pragma unroll
    for (int e = 0; e < 4; e++) {
        const int i = ig + e;
        #pragma unroll
        for (int c = 0; c < 4; c++)
            if (jg + c > i) a[e][c] = 0.f;
        float rs = a[e][0] + a[e][1] + a[e][2] + a[e][3];
        rs += __shfl_xor_sync(0xffffffffu, rs, 1);
        rs += __shfl_xor_sync(0xffffffffu, rs, 2);
        rs += __shfl_xor_sync(0xffffffffu, rs, 4);
        rs += __shfl_xor_sync(0xffffffffu, rs, 8);
        den[e] = qz[e] + rs + 1e-6f;
        *(float4*)(Am + i * CST + jg) = make_float4(a[e][0], a[e][1], a[e][2], a[e][3]);
    }
    __syncthreads();

    float acc[4][4];
    #pragma unroll
    for (int e = 0; e < 4; e++)
        #pragma unroll
        for (int c = 0; c < 4; c++) acc[e][c] = 0.f;

    #pragma unroll 4
    for (int m = 0; m < DH; m++) {
        float4 s4 = *(const float4*)(Sp + m * CST + jg);
        #pragma unroll
        for (int e = 0; e < 4; e++) {
            const float qv = qs[(ig + e) * CST + m];
            acc[e][0] = fmaf(qv, s4.x, acc[e][0]);
            acc[e][1] = fmaf(qv, s4.y, acc[e][1]);
            acc[e][2] = fmaf(qv, s4.z, acc[e][2]);
            acc[e][3] = fmaf(qv, s4.w, acc[e][3]);
        }
    }
    const int jmax = ig + 3;
    for (int j = 0; j <= jmax; j++) {
        float4 v4 = *(const float4*)(vs + j * CST + jg);
        #pragma unroll
        for (int e = 0; e < 4; e++) {
            const float av = Am[(ig + e) * CST + j];
            acc[e][0] = fmaf(av, v4.x, acc[e][0]);
            acc[e][1] = fmaf(av, v4.y, acc[e][1]);
            acc[e][2] = fmaf(av, v4.z, acc[e][2]);
            acc[e][3] = fmaf(av, v4.w, acc[e][3]);
        }
    }

    #pragma unroll
    for (int e = 0; e < 4; e++) {
        const float inv = 1.f / den[e];
        __half* op = Outh + gbase + (size_t)(ig + e) * D_MODEL + jg;
        *(__half2*)(op)     = __floats2half2_rn(acc[e][0] * inv, acc[e][1] * inv);
        *(__half2*)(op + 2) = __floats2half2_rn(acc[e][2] * inv, acc[e][3] * inv);
    }
}

// ---------------- LayerNorm: out = LN(a + r) * g + b ; optional fp16 copy ----------------
__global__ __launch_bounds__(256) void ln_kernel(
    float* __restrict__ out, const float* __restrict__ a,
    const float* __restrict__ r, const float* __restrict__ gam,
    const float* __restrict__ bet, __half* __restrict__ outh)
{
    const int row = blockIdx.x;
    const int tid = threadIdx.x;
    const float* pa = a + (size_t)row * D_MODEL;
    const float* pr = r + (size_t)row * D_MODEL;

    float v[4];
    float s = 0.f, ss = 0.f;
    #pragma unroll
    for (int i = 0; i < 4; i++) {
        int idx = tid + i * 256;
        float t = pa[idx] + pr[idx];
        v[i] = t; s += t; ss = fmaf(t, t, ss);
    }

    __shared__ float red[18];
    #pragma unroll
    for (int o = 16; o; o >>= 1) {
        s  += __shfl_xor_sync(0xffffffffu, s,  o);
        ss += __shfl_xor_sync(0xffffffffu, ss, o);
    }
    const int w = tid >> 5, lane = tid & 31;
    __shared__ float rw[16];
    if (lane == 0) { rw[w] = s; rw[w + 8] = ss; }
    __syncthreads();
    if (tid == 0) {
        float S0 = 0.f, S1 = 0.f;
        #pragma unroll
        for (int i = 0; i < 8; i++) { S0 += rw[i]; S1 += rw[i + 8]; }
        red[16] = S0; red[17] = S1;
    }
    __syncthreads();

    const float mean = red[16] * (1.f / 1024.f);
    const float var  = red[17] * (1.f / 1024.f) - mean * mean;
    const float inv  = rsqrtf(var + 1e-5f);

    float* po = out + (size_t)row * D_MODEL;
    __half* ph = (outh != nullptr) ? outh + (size_t)row * D_MODEL : nullptr;
    #pragma unroll
    for (int i = 0; i < 4; i++) {
        int idx = tid + i * 256;
        float o = (v[i] - mean) * inv * gam[idx] + bet[idx];
        po[idx] = o;
        if (ph) ph[idx] = __float2half_rn(o);
    }
}

// ---------------- launch ----------------
extern "C" void kernel_launch(void* const* d_in, const int* in_sizes, int n_in,
                              void* d_out, int out_size)
{
    const float* x    = (const float*)d_in[0];
    const float* Wq   = (const float*)d_in[1];
    const float* bq   = (const float*)d_in[2];
    const float* Wk   = (const float*)d_in[3];
    const float* bk   = (const float*)d_in[4];
    const float* Wv   = (const float*)d_in[5];
    const float* bv   = (const float*)d_in[6];
    const float* Wo   = (const float*)d_in[7];
    const float* bo   = (const float*)d_in[8];
    const float* omg  = (const float*)d_in[9];
    const float* ln1g = (const float*)d_in[10];
    const float* ln1b = (const float*)d_in[11];
    const float* ln2g = (const float*)d_in[12];
    const float* ln2b = (const float*)d_in[13];
    const float* W1   = (const float*)d_in[14];
    const float* bf1  = (const float*)d_in[15];
    const float* W2   = (const float*)d_in[16];
    const float* bf2  = (const float*)d_in[17];
    float* out = (float*)d_out;

    float *cur, *q, *k, *v, *h, *gS, *gZ;
    __half *xh, *hh, *ah, *fh;
    cudaGetSymbolAddress((void**)&cur, g_cur);
    cudaGetSymbolAddress((void**)&q,   g_q);
    cudaGetSymbolAddress((void**)&k,   g_k);
    cudaGetSymbolAddress((void**)&v,   g_v);
    cudaGetSymbolAddress((void**)&h,   g_h);
    cudaGetSymbolAddress((void**)&gS,  g_S);
    cudaGetSymbolAddress((void**)&gZ,  g_Z);
    cudaGetSymbolAddress((void**)&xh,  g_xh);
    cudaGetSymbolAddress((void**)&hh,  g_hh);
    cudaGetSymbolAddress((void**)&ah,  g_ah);
    cudaGetSymbolAddress((void**)&fh,  g_fh);

    cudaFuncSetAttribute(mma_gemm_h, cudaFuncAttributeMaxDynamicSharedMemorySize, GEMM_SMEM);
    cudaFuncSetAttribute(chunk_sums_kernel, cudaFuncAttributeMaxDynamicSharedMemorySize, SUMS_SMEM);
    cudaFuncSetAttribute(chunk_attn_kernel, cudaFuncAttributeMaxDynamicSharedMemorySize, ATTN_SMEM);

    // prep: fp16-convert layer-0 activation
    const int nX4 = NTOK * D_MODEL / 4;
    half_kernel<<<nX4 / 256, 256>>>(x, xh, nX4);

    const dim3 gQKV(D_MODEL / 128, NTOK / 128, 3);
    const dim3 gD(D_MODEL / 128, NTOK / 128, 1);
    const dim3 gF(DFF_DIM / 128, NTOK / 128, 1);
    const dim3 gCh(NCHUNK, 32);
    const int  gPref = (32 * 4096) / 256;

    for (int l = 0; l < NLAYER; l++) {
        const size_t wDD  = (size_t)l * D_MODEL * D_MODEL;
        const size_t wDF  = (size_t)l * D_MODEL * DFF_DIM;
        const size_t bD   = (size_t)l * D_MODEL;
        const size_t bF   = (size_t)l * DFF_DIM;
        const size_t oOff = (size_t)l * DH * 32;
        const float* resA = (l == 0) ? x : cur;

        mma_gemm_h<<<gQKV, 512, GEMM_SMEM>>>(xh,
            Wq + wDD, Wk + wDD, Wv + wDD,
            bq + bD, bk + bD, bv + bD,
            q, k, v,
            (__half*)nullptr, (__half*)nullptr, (__half*)nullptr,
            NTOK, D_MODEL, D_MODEL, 0);

        chunk_sums_kernel<<<gCh, 256, SUMS_SMEM>>>(k, v, omg + oOff, gS, gZ);
        chunk_prefix_kernel<<<gPref, 256>>>(gS, gZ);
        chunk_attn_kernel<<<gCh, 256, ATTN_SMEM>>>(q, k, v, omg + oOff, gS, gZ, ah);

        mma_gemm_h<<<gD, 512, GEMM_SMEM>>>(ah,
            Wo + wDD, Wo + wDD, Wo + wDD,
            bo + bD, bo + bD, bo + bD,
            k, k, k,
            (__half*)nullptr, (__half*)nullptr, (__half*)nullptr,
            NTOK, D_MODEL, D_MODEL, 0);
        ln_kernel<<<NTOK, 256>>>(h, resA, k, ln1g + bD, ln1b + bD, hh);

        mma_gemm_h<<<gF, 512, GEMM_SMEM>>>(hh,
            W1 + wDF, W1 + wDF, W1 + wDF,
            bf1 + bF, bf1 + bF, bf1 + bF,
            (float*)nullptr, (float*)nullptr, (float*)nullptr,
            fh, fh, fh,
            NTOK, DFF_DIM, D_MODEL, 1);
        mma_gemm_h<<<gD, 512, GEMM_SMEM>>>(fh,
            W2 + wDF, W2 + wDF, W2 + wDF,
            bf2 + bD, bf2 + bD, bf2 + bD,
            v, v, v,
            (__half*)nullptr, (__half*)nullptr, (__half*)nullptr,
            NTOK, D_MODEL, DFF_DIM, 0);

        const bool last = (l == NLAYER - 1);
        float* dst = last ? out : cur;
        ln_kernel<<<NTOK, 256>>>(dst, h, v, ln2g + bD, ln2b + bD, last ? (__half*)nullptr : xh);
    }
}